// round 7
// baseline (speedup 1.0000x reference)
#include <cuda_runtime.h>
#include <cstdint>

#define DEVINL static __device__ __forceinline__

#define N_EDGES 600000
#define N_NODES 50000
#define ETILES 4688     // ceil(600000/128)
#define NTILES 391      // ceil(50000/128)
#define GRID_E 148

// Padded tile geometry: 128 rows x 128 cols fp32, row stride 544B (136 floats).
// 4B-bank of (r*544 + 4*(8k+lm)) = (8*(r&7) + lm + c) mod 32 -> conflict-free
// for the mma access pattern, with ADDRESSES LINEAR in k/mi/nt (LDS immediates).
#define RSTRIDE 544
#define TILE_BYTES (128 * RSTRIDE)   // 69632

// Node projection scratch (b1 folded into srcproj). Static device mem (no allocs).
static __device__ float g_srcproj[(size_t)N_NODES * 128];
static __device__ float g_dstproj[(size_t)N_NODES * 128];

// ---------------- helpers ----------------

DEVINL uint32_t smem_u32(const void* p) {
    uint32_t a;
    asm("{ .reg .u64 t; cvta.to.shared.u64 t, %1; cvt.u32.u64 %0, t; }" : "=r"(a) : "l"(p));
    return a;
}
DEVINL uint32_t tf32c(float f) {
    uint32_t r;
    asm("cvt.rna.tf32.f32 %0, %1;" : "=r"(r) : "f"(f));
    return r;
}
DEVINL uint32_t lds32(uint32_t a) {
    uint32_t v;
    asm volatile("ld.shared.b32 %0, [%1];" : "=r"(v) : "r"(a));
    return v;
}
DEVINL float4 lds128f(uint32_t a) {
    float4 v;
    asm volatile("ld.shared.v4.f32 {%0,%1,%2,%3}, [%4];"
                 : "=f"(v.x), "=f"(v.y), "=f"(v.z), "=f"(v.w) : "r"(a));
    return v;
}
DEVINL void sts64f(uint32_t a, float x, float y) {
    asm volatile("st.shared.v2.f32 [%0], {%1,%2};" :: "r"(a), "f"(x), "f"(y));
}
DEVINL void sts128(uint32_t a, uint32_t x, uint32_t y, uint32_t z, uint32_t w) {
    asm volatile("st.shared.v4.b32 [%0], {%1,%2,%3,%4};" :: "r"(a), "r"(x), "r"(y), "r"(z), "r"(w));
}
DEVINL void cpasync16(uint32_t s, const void* g, int srcbytes) {
    asm volatile("cp.async.cg.shared.global [%0], [%1], 16, %2;"
                 :: "r"(s), "l"(g), "r"(srcbytes));
}
DEVINL void cpcommit() { asm volatile("cp.async.commit_group;" ::: "memory"); }
DEVINL void cpwait0()  { asm volatile("cp.async.wait_group 0;" ::: "memory"); }

// silu(x) = x*sigmoid(x) = h + h*tanh(h), h = x/2  (1 MUFU)
DEVINL float silu_f(float x) {
    float h = 0.5f * x, t;
    asm("tanh.approx.f32 %0, %1;" : "=f"(t) : "f"(h));
    return fmaf(h, t, h);
}

// Out-dim permutation: n = 32c+8a+2b+e -> 32c+8b+2a+e  (swap 2-bit fields a,b).
// Applied to weight SMEM rows so that a thread's D-fragment columns are the
// CONTIGUOUS logical columns 32*cg + 8*lm + {0..7}.
DEVINL int permn(int n) {
    return (n & 0x61) | ((n & 6) << 2) | ((n >> 2) & 6);
}

// Padded-tile address of element (row r, float-col c).
DEVINL uint32_t adr(uint32_t b, int r, int c) {
    return b + (uint32_t)r * (uint32_t)RSTRIDE + (uint32_t)c * 4u;
}

// m16n8k8 tf32 HMMA (base-target PTX)
DEVINL void mma8(float* d, const uint32_t* a, uint32_t b0, uint32_t b1) {
    asm volatile(
        "mma.sync.aligned.m16n8k8.row.col.f32.tf32.tf32.f32 "
        "{%0,%1,%2,%3}, {%4,%5,%6,%7}, {%8,%9}, {%0,%1,%2,%3};"
        : "+f"(d[0]), "+f"(d[1]), "+f"(d[2]), "+f"(d[3])
        : "r"(a[0]), "r"(a[1]), "r"(a[2]), "r"(a[3]), "r"(b0), "r"(b1));
}

// Load [128 out][128 in] row-major weight into padded SMEM (out-rows permuted).
DEVINL void load_weight(uint32_t sbW, const float* __restrict__ W, int tid) {
#pragma unroll 1
    for (int i = tid; i < 4096; i += 512) {
        int n = i >> 5, k4 = (i & 31) << 2;
        float4 v = __ldg((const float4*)W + i);
        sts128(adr(sbW, permn(n), k4), tf32c(v.x), tf32c(v.y), tf32c(v.z), tf32c(v.w));
    }
}

// 128x128x128 GEMM, 16 warps. Warp w: rg=w>>2 rows [32rg,+32), cg=w&3 cols [32cg,+32).
// acc[(mi*4+nt)*4 + 2*h + e]; logical col of (nt,e) = 32cg + 8lm + 2nt + e.
// All load addresses are base + compile-time immediates (2 base regs total).
DEVINL void gemm512(uint32_t sbA, uint32_t sbW, int rg, int cg, int lq, int lm,
                    float acc[32]) {
    const uint32_t bA = sbA + (uint32_t)(32 * rg + lq) * RSTRIDE + 4u * lm;
    const uint32_t bB = sbW + (uint32_t)(32 * cg + lq) * RSTRIDE + 4u * lm;
#pragma unroll
    for (int kk = 0; kk < 16; kk++) {
        uint32_t a[2][4];
#pragma unroll
        for (int mi = 0; mi < 2; mi++) {
            const uint32_t r = bA + (uint32_t)(mi * 16 * RSTRIDE + kk * 32);
            a[mi][0] = lds32(r);
            a[mi][1] = lds32(r + 8 * RSTRIDE);
            a[mi][2] = lds32(r + 16);
            a[mi][3] = lds32(r + 8 * RSTRIDE + 16);
        }
#pragma unroll
        for (int nt = 0; nt < 4; nt++) {
            const uint32_t rb = bB + (uint32_t)(nt * 8 * RSTRIDE + kk * 32);
            uint32_t b0 = lds32(rb);
            uint32_t b1 = lds32(rb + 16);
            mma8(acc + nt * 4,      a[0], b0, b1);
            mma8(acc + 16 + nt * 4, a[1], b0, b1);
        }
    }
}

// Extract thread's 8 contiguous logical cols (j = 2*nt+e) for row-rep (mi,h).
#define ACCJ(mi, h, j) acc[((mi) * 4 + ((j) >> 1)) * 4 + 2 * (h) + ((j) & 1)]

// ---------------- node projection kernel ----------------
// SMEM: Ws[0,69632) Wd[69632,139264) A[139264,208896) b1[208896,+512)
#define NODE_SMEM 209408

__global__ void __launch_bounds__(512, 1)
node_kernel(const float* __restrict__ nfeat, const float* __restrict__ Ws,
            const float* __restrict__ Wd, const float* __restrict__ b1,
            float* __restrict__ nfeat_out) {
    extern __shared__ char smem[];
    const uint32_t sb = smem_u32(smem);
    const uint32_t sWS = sb, sWD = sb + TILE_BYTES, sAB = sb + 2 * TILE_BYTES;
    const uint32_t sB1 = sb + 3 * TILE_BYTES;
    const int tid = threadIdx.x, w = tid >> 5, lane = tid & 31;
    const int lq = lane >> 2, lm = lane & 3, rg = w >> 2, cg = w & 3;

    load_weight(sWS, Ws, tid);
    load_weight(sWD, Wd, tid);
    if (tid < 128) ((float*)(smem + 3 * TILE_BYTES))[tid] = __ldg(b1 + tid);

    const int base = blockIdx.x * 128;
#pragma unroll
    for (int i = 0; i < 8; i++) {
        const int f4 = tid + 512 * i;
        const int row = f4 >> 5, c4 = f4 & 31;
        const int ng = base + row;
        const bool v = ng < N_NODES;
        float4 x = v ? __ldg((const float4*)(nfeat + (size_t)ng * 128) + c4)
                     : make_float4(0.f, 0.f, 0.f, 0.f);
        // fused nfeat passthrough (exact fp32 copy)
        if (v) *((float4*)(nfeat_out + (size_t)ng * 128) + c4) = x;
        sts128(adr(sAB, row, c4 * 4), tf32c(x.x), tf32c(x.y), tf32c(x.z), tf32c(x.w));
    }
    __syncthreads();

    const int Lb = 32 * cg + 8 * lm;                 // thread's logical col base
    const float4 bb0 = lds128f(sB1 + (uint32_t)Lb * 4);
    const float4 bb1 = lds128f(sB1 + (uint32_t)Lb * 4 + 16);

    float acc[32];
#pragma unroll
    for (int i = 0; i < 32; i++) acc[i] = 0.f;
    gemm512(sAB, sWS, rg, cg, lq, lm, acc);
#pragma unroll
    for (int mi = 0; mi < 2; mi++)
#pragma unroll
    for (int h = 0; h < 2; h++) {
        const int ng = base + 32 * rg + 16 * mi + 8 * h + lq;
        if (ng < N_NODES) {
            float4 o0, o1;
            o0.x = ACCJ(mi, h, 0) + bb0.x;  o0.y = ACCJ(mi, h, 1) + bb0.y;
            o0.z = ACCJ(mi, h, 2) + bb0.z;  o0.w = ACCJ(mi, h, 3) + bb0.w;
            o1.x = ACCJ(mi, h, 4) + bb1.x;  o1.y = ACCJ(mi, h, 5) + bb1.y;
            o1.z = ACCJ(mi, h, 6) + bb1.z;  o1.w = ACCJ(mi, h, 7) + bb1.w;
            float4* p = (float4*)(g_srcproj + (size_t)ng * 128 + Lb);
            p[0] = o0; p[1] = o1;
        }
    }

#pragma unroll
    for (int i = 0; i < 32; i++) acc[i] = 0.f;
    gemm512(sAB, sWD, rg, cg, lq, lm, acc);
#pragma unroll
    for (int mi = 0; mi < 2; mi++)
#pragma unroll
    for (int h = 0; h < 2; h++) {
        const int ng = base + 32 * rg + 16 * mi + 8 * h + lq;
        if (ng < N_NODES) {
            float4 o0, o1;
            o0.x = ACCJ(mi, h, 0);  o0.y = ACCJ(mi, h, 1);
            o0.z = ACCJ(mi, h, 2);  o0.w = ACCJ(mi, h, 3);
            o1.x = ACCJ(mi, h, 4);  o1.y = ACCJ(mi, h, 5);
            o1.z = ACCJ(mi, h, 6);  o1.w = ACCJ(mi, h, 7);
            float4* p = (float4*)(g_dstproj + (size_t)ng * 128 + Lb);
            p[0] = o0; p[1] = o1;
        }
    }
}

// ---------------- fused edge kernel (persistent, 512 thr) ----------------
// SMEM: We[0,69632) Wo[69632,139264) A[139264,208896) LN[208896,+4096)
//       bo@212992 gamma@213504 beta@214016
#define EDGE_SMEM 214528

// Prefetch one 128x128 fp32 tile of efeat into padded SMEM via cp.async.
DEVINL void prefetch_efeat(uint32_t sAB, const float* __restrict__ efeat,
                           int tile, int tid) {
    const int base = tile * 128;
#pragma unroll
    for (int i = 0; i < 8; i++) {
        const int f4 = tid + 512 * i;
        const int row = f4 >> 5, c4 = f4 & 31;
        const int e = base + row;
        const bool v = e < N_EDGES;
        const float* g = efeat + (size_t)(v ? e : 0) * 128 + c4 * 4;
        cpasync16(adr(sAB, row, c4 * 4), g, v ? 16 : 0);
    }
    cpcommit();
}

__global__ void __launch_bounds__(512, 1)
edge_kernel(const float* __restrict__ efeat, const int* __restrict__ src,
            const int* __restrict__ dst, const float* __restrict__ We,
            const float* __restrict__ Wo, const float* __restrict__ bo,
            const float* __restrict__ gamma, const float* __restrict__ beta,
            float* __restrict__ out) {
    extern __shared__ char smem[];
    const uint32_t sb = smem_u32(smem);
    const uint32_t sWE = sb, sWO = sb + TILE_BYTES, sAB = sb + 2 * TILE_BYTES;
    const uint32_t sLN = sb + 3 * TILE_BYTES;
    const uint32_t sBO = sLN + 4096, sGA = sBO + 512, sBE = sGA + 512;
    const int tid = threadIdx.x, w = tid >> 5, lane = tid & 31;
    const int lq = lane >> 2, lm = lane & 3, rg = w >> 2, cg = w & 3;

    load_weight(sWE, We, tid);
    load_weight(sWO, Wo, tid);
    if (tid < 128) {
        ((float*)(smem + (sBO - sb)))[tid] = __ldg(bo + tid);
        ((float*)(smem + (sGA - sb)))[tid] = __ldg(gamma + tid);
        ((float*)(smem + (sBE - sb)))[tid] = __ldg(beta + tid);
    }
    // prologue: prefetch first tile (raw fp32; tf32 mma truncates low bits)
    prefetch_efeat(sAB, efeat, blockIdx.x, tid);
    __syncthreads();

    const int Lb = 32 * cg + 8 * lm;                 // thread's logical col base
    const float4 bo0 = lds128f(sBO + (uint32_t)Lb * 4);
    const float4 bo1 = lds128f(sBO + (uint32_t)Lb * 4 + 16);
    const float4 ga0 = lds128f(sGA + (uint32_t)Lb * 4);
    const float4 ga1 = lds128f(sGA + (uint32_t)Lb * 4 + 16);
    const float4 be0 = lds128f(sBE + (uint32_t)Lb * 4);
    const float4 be1 = lds128f(sBE + (uint32_t)Lb * 4 + 16);

    for (int tile = blockIdx.x; tile < ETILES; tile += GRID_E) {
        const int base = tile * 128;
        cpwait0();
        __syncthreads();                      // (a) efeat tile ready in A

        // prefetch gather indices early (consumed after GEMM1)
        int si[4], di[4];
        bool vr[4];
#pragma unroll
        for (int mi = 0; mi < 2; mi++)
#pragma unroll
        for (int h = 0; h < 2; h++) {
            const int e = base + 32 * rg + 16 * mi + 8 * h + lq;
            const bool v = e < N_EDGES;
            vr[mi * 2 + h] = v;
            si[mi * 2 + h] = v ? __ldg(src + e) : 0;
            di[mi * 2 + h] = v ? __ldg(dst + e) : 0;
        }

        float acc[32];
#pragma unroll
        for (int i = 0; i < 32; i++) acc[i] = 0.f;
        gemm512(sAB, sWE, rg, cg, lq, lm, acc);   // h-pre = efeat @ We^T
        __syncthreads();                      // (c) all warps done reading A

        // epilogue1: + srcproj[src] (b1 folded) + dstproj[dst], SiLU, act -> A
#pragma unroll
        for (int mi = 0; mi < 2; mi++)
#pragma unroll
        for (int h = 0; h < 2; h++) {
            const int R = 32 * rg + 16 * mi + 8 * h + lq;
            const float4* ps = (const float4*)(g_srcproj + (size_t)si[mi * 2 + h] * 128 + Lb);
            const float4* pd = (const float4*)(g_dstproj + (size_t)di[mi * 2 + h] * 128 + Lb);
            float4 s0 = __ldg(ps), s1 = __ldg(ps + 1);
            float4 d0 = __ldg(pd), d1 = __ldg(pd + 1);
            float x0 = silu_f(ACCJ(mi, h, 0) + s0.x + d0.x);
            float x1 = silu_f(ACCJ(mi, h, 1) + s0.y + d0.y);
            float x2 = silu_f(ACCJ(mi, h, 2) + s0.z + d0.z);
            float x3 = silu_f(ACCJ(mi, h, 3) + s0.w + d0.w);
            float x4 = silu_f(ACCJ(mi, h, 4) + s1.x + d1.x);
            float x5 = silu_f(ACCJ(mi, h, 5) + s1.y + d1.y);
            float x6 = silu_f(ACCJ(mi, h, 6) + s1.z + d1.z);
            float x7 = silu_f(ACCJ(mi, h, 7) + s1.w + d1.w);
            sts128(adr(sAB, R, Lb),     tf32c(x0), tf32c(x1), tf32c(x2), tf32c(x3));
            sts128(adr(sAB, R, Lb + 4), tf32c(x4), tf32c(x5), tf32c(x6), tf32c(x7));
        }
        __syncthreads();                      // (d) act tile complete

#pragma unroll
        for (int i = 0; i < 32; i++) acc[i] = 0.f;
        gemm512(sAB, sWO, rg, cg, lq, lm, acc);   // o-pre = act @ Wo^T

        // epilogue2a: + bo, LayerNorm partials (quad shfl + cross-warp SMEM)
#pragma unroll
        for (int mi = 0; mi < 2; mi++)
#pragma unroll
        for (int h = 0; h < 2; h++) {
            float s = 0.f, q = 0.f;
#pragma unroll
            for (int j = 0; j < 8; j++) {
                const float b = (j < 4) ? ((const float*)&bo0)[j] : ((const float*)&bo1)[j - 4];
                float x = ACCJ(mi, h, j) + b;
                ACCJ(mi, h, j) = x;
                s += x;
                q += x * x;
            }
            s += __shfl_xor_sync(0xffffffffu, s, 1);
            q += __shfl_xor_sync(0xffffffffu, q, 1);
            s += __shfl_xor_sync(0xffffffffu, s, 2);
            q += __shfl_xor_sync(0xffffffffu, q, 2);
            if (lm == 0) {
                const int R = 32 * rg + 16 * mi + 8 * h + lq;
                sts64f(sLN + (uint32_t)(cg * 128 + R) * 8, s, q);
            }
        }
        __syncthreads();                      // (e) LN partials visible; A free

        // prefetch next tile's efeat into A (overlaps epilogue2b)
        if (tile + GRID_E < ETILES)
            prefetch_efeat(sAB, efeat, tile + GRID_E, tid);

        // epilogue2b: normalize, affine, + residual efeat (L2-hot), store
#pragma unroll
        for (int mi = 0; mi < 2; mi++)
#pragma unroll
        for (int h = 0; h < 2; h++) {
            const int R = 32 * rg + 16 * mi + 8 * h + lq;
            const int e = base + R;
            const bool v = vr[mi * 2 + h];
            float2 p0 = *(float2*)(smem + (sLN - sb) + (uint32_t)R * 8);
            float2 p1 = *(float2*)(smem + (sLN - sb) + (uint32_t)(128 + R) * 8);
            float2 p2 = *(float2*)(smem + (sLN - sb) + (uint32_t)(256 + R) * 8);
            float2 p3 = *(float2*)(smem + (sLN - sb) + (uint32_t)(384 + R) * 8);
            const float mu  = (p0.x + p1.x + p2.x + p3.x) * 0.0078125f;
            const float var = (p0.y + p1.y + p2.y + p3.y) * 0.0078125f - mu * mu;
            const float rs  = rsqrtf(var + 1e-5f);
            const float4* pe = (const float4*)(efeat + (size_t)(v ? e : 0) * 128 + Lb);
            float4 r0 = v ? __ldg(pe)     : make_float4(0.f, 0.f, 0.f, 0.f);
            float4 r1 = v ? __ldg(pe + 1) : make_float4(0.f, 0.f, 0.f, 0.f);
            float4 o0, o1;
            o0.x = (ACCJ(mi, h, 0) - mu) * rs * ga0.x + be0.x + r0.x;
            o0.y = (ACCJ(mi, h, 1) - mu) * rs * ga0.y + be0.y + r0.y;
            o0.z = (ACCJ(mi, h, 2) - mu) * rs * ga0.z + be0.z + r0.z;
            o0.w = (ACCJ(mi, h, 3) - mu) * rs * ga0.w + be0.w + r0.w;
            o1.x = (ACCJ(mi, h, 4) - mu) * rs * ga1.x + be1.x + r1.x;
            o1.y = (ACCJ(mi, h, 5) - mu) * rs * ga1.y + be1.y + r1.y;
            o1.z = (ACCJ(mi, h, 6) - mu) * rs * ga1.z + be1.z + r1.z;
            o1.w = (ACCJ(mi, h, 7) - mu) * rs * ga1.w + be1.w + r1.w;
            if (v) {
                float4* po = (float4*)(out + (size_t)e * 128 + Lb);
                po[0] = o0; po[1] = o1;
            }
        }
    }
}

// ---------------- launch ----------------

extern "C" void kernel_launch(void* const* d_in, const int* in_sizes, int n_in,
                              void* d_out, int out_size) {
    const float* efeat = (const float*)d_in[0];
    const float* nfeat = (const float*)d_in[1];
    const int*   src   = (const int*)d_in[2];
    const int*   dst   = (const int*)d_in[3];
    const float* We    = (const float*)d_in[4];
    const float* Ws    = (const float*)d_in[5];
    const float* Wd    = (const float*)d_in[6];
    const float* b1    = (const float*)d_in[7];
    const float* Wo    = (const float*)d_in[8];
    const float* bo    = (const float*)d_in[9];
    const float* gamma = (const float*)d_in[10];
    const float* beta  = (const float*)d_in[11];
    float* out = (float*)d_out;

    cudaFuncSetAttribute(node_kernel, cudaFuncAttributeMaxDynamicSharedMemorySize, NODE_SMEM);
    cudaFuncSetAttribute(edge_kernel, cudaFuncAttributeMaxDynamicSharedMemorySize, EDGE_SMEM);

    // node kernel also writes the nfeat passthrough output
    node_kernel<<<NTILES, 512, NODE_SMEM>>>(nfeat, Ws, Wd, b1,
                                            out + (size_t)N_EDGES * 128);
    edge_kernel<<<GRID_E, 512, EDGE_SMEM>>>(efeat, src, dst, We, Wo, bo, gamma, beta, out);
}

// round 8
// speedup vs baseline: 1.2246x; 1.2246x over previous
#include <cuda_runtime.h>
#include <cstdint>

#define DEVINL static __device__ __forceinline__

#define N_EDGES 600000
#define N_NODES 50000
#define ETILES 4688     // ceil(600000/128)
#define NTILES 391      // ceil(50000/128)
#define GRID_E 148

// Padded tile geometry: 128 rows x 128 cols fp32, row stride 528B (132 floats).
// 132 mod 32 = 4  =>  bank(r*132 + lm) = (4*lq + lm + c) mod 32 over the warp's
// (lq,lm) grid -> ALL 32 LANES DISTINCT banks for the mma access pattern, with
// addresses LINEAR in k/mi/nt (LDS immediates, 2 base regs per GEMM).
// (R7 used 544B = 8 mod 32, which has period 4 in lq -> 2-way conflicts.)
#define RSTRIDE 528
#define TILE_BYTES (128 * RSTRIDE)   // 67584

// Node projection scratch (b1 folded into srcproj). Static device mem (no allocs).
static __device__ float g_srcproj[(size_t)N_NODES * 128];
static __device__ float g_dstproj[(size_t)N_NODES * 128];

// ---------------- helpers ----------------

DEVINL uint32_t smem_u32(const void* p) {
    uint32_t a;
    asm("{ .reg .u64 t; cvta.to.shared.u64 t, %1; cvt.u32.u64 %0, t; }" : "=r"(a) : "l"(p));
    return a;
}
DEVINL uint32_t tf32c(float f) {
    uint32_t r;
    asm("cvt.rna.tf32.f32 %0, %1;" : "=r"(r) : "f"(f));
    return r;
}
DEVINL uint32_t lds32(uint32_t a) {
    uint32_t v;
    asm volatile("ld.shared.b32 %0, [%1];" : "=r"(v) : "r"(a));
    return v;
}
DEVINL float4 lds128f(uint32_t a) {
    float4 v;
    asm volatile("ld.shared.v4.f32 {%0,%1,%2,%3}, [%4];"
                 : "=f"(v.x), "=f"(v.y), "=f"(v.z), "=f"(v.w) : "r"(a));
    return v;
}
DEVINL void sts64f(uint32_t a, float x, float y) {
    asm volatile("st.shared.v2.f32 [%0], {%1,%2};" :: "r"(a), "f"(x), "f"(y));
}
DEVINL void sts128(uint32_t a, uint32_t x, uint32_t y, uint32_t z, uint32_t w) {
    asm volatile("st.shared.v4.b32 [%0], {%1,%2,%3,%4};" :: "r"(a), "r"(x), "r"(y), "r"(z), "r"(w));
}
DEVINL void cpasync16(uint32_t s, const void* g, int srcbytes) {
    asm volatile("cp.async.cg.shared.global [%0], [%1], 16, %2;"
                 :: "r"(s), "l"(g), "r"(srcbytes));
}
DEVINL void cpcommit() { asm volatile("cp.async.commit_group;" ::: "memory"); }
DEVINL void cpwait0()  { asm volatile("cp.async.wait_group 0;" ::: "memory"); }

// silu(x) = x*sigmoid(x) = h + h*tanh(h), h = x/2  (1 MUFU)
DEVINL float silu_f(float x) {
    float h = 0.5f * x, t;
    asm("tanh.approx.f32 %0, %1;" : "=f"(t) : "f"(h));
    return fmaf(h, t, h);
}

// Out-dim permutation: n = 32c+8a+2b+e -> 32c+8b+2a+e  (swap 2-bit fields a,b).
// Applied to weight SMEM rows so that a thread's D-fragment columns are the
// CONTIGUOUS logical columns 32*cg + 8*lm + {0..7}.
DEVINL int permn(int n) {
    return (n & 0x61) | ((n & 6) << 2) | ((n >> 2) & 6);
}

// Padded-tile address of element (row r, float-col c).
DEVINL uint32_t adr(uint32_t b, int r, int c) {
    return b + (uint32_t)r * (uint32_t)RSTRIDE + (uint32_t)c * 4u;
}

// m16n8k8 tf32 HMMA (base-target PTX)
DEVINL void mma8(float* d, const uint32_t* a, uint32_t b0, uint32_t b1) {
    asm volatile(
        "mma.sync.aligned.m16n8k8.row.col.f32.tf32.tf32.f32 "
        "{%0,%1,%2,%3}, {%4,%5,%6,%7}, {%8,%9}, {%0,%1,%2,%3};"
        : "+f"(d[0]), "+f"(d[1]), "+f"(d[2]), "+f"(d[3])
        : "r"(a[0]), "r"(a[1]), "r"(a[2]), "r"(a[3]), "r"(b0), "r"(b1));
}

// Load [128 out][128 in] row-major weight into padded SMEM (out-rows permuted).
DEVINL void load_weight(uint32_t sbW, const float* __restrict__ W, int tid) {
#pragma unroll 1
    for (int i = tid; i < 4096; i += 512) {
        int n = i >> 5, k4 = (i & 31) << 2;
        float4 v = __ldg((const float4*)W + i);
        sts128(adr(sbW, permn(n), k4), tf32c(v.x), tf32c(v.y), tf32c(v.z), tf32c(v.w));
    }
}

// 128x128x128 GEMM, 16 warps. Warp w: rg=w>>2 rows [32rg,+32), cg=w&3 cols [32cg,+32).
// acc[(mi*4+nt)*4 + 2*h + e]; logical col of (nt,e) = 32cg + 8lm + 2nt + e.
// All load addresses are base + compile-time immediates (2 base regs total).
DEVINL void gemm512(uint32_t sbA, uint32_t sbW, int rg, int cg, int lq, int lm,
                    float acc[32]) {
    const uint32_t bA = sbA + (uint32_t)(32 * rg + lq) * RSTRIDE + 4u * lm;
    const uint32_t bB = sbW + (uint32_t)(32 * cg + lq) * RSTRIDE + 4u * lm;
#pragma unroll
    for (int kk = 0; kk < 16; kk++) {
        uint32_t a[2][4];
#pragma unroll
        for (int mi = 0; mi < 2; mi++) {
            const uint32_t r = bA + (uint32_t)(mi * 16 * RSTRIDE + kk * 32);
            a[mi][0] = lds32(r);
            a[mi][1] = lds32(r + 8 * RSTRIDE);
            a[mi][2] = lds32(r + 16);
            a[mi][3] = lds32(r + 8 * RSTRIDE + 16);
        }
#pragma unroll
        for (int nt = 0; nt < 4; nt++) {
            const uint32_t rb = bB + (uint32_t)(nt * 8 * RSTRIDE + kk * 32);
            uint32_t b0 = lds32(rb);
            uint32_t b1 = lds32(rb + 16);
            mma8(acc + nt * 4,      a[0], b0, b1);
            mma8(acc + 16 + nt * 4, a[1], b0, b1);
        }
    }
}

// Extract thread's 8 contiguous logical cols (j = 2*nt+e) for row-rep (mi,h).
#define ACCJ(mi, h, j) acc[((mi) * 4 + ((j) >> 1)) * 4 + 2 * (h) + ((j) & 1)]

// ---------------- node projection kernel ----------------
// SMEM: Ws[0,67584) Wd[67584,135168) A[135168,202752) b1[202752,+512)
#define NODE_SMEM 203264

__global__ void __launch_bounds__(512, 1)
node_kernel(const float* __restrict__ nfeat, const float* __restrict__ Ws,
            const float* __restrict__ Wd, const float* __restrict__ b1,
            float* __restrict__ nfeat_out) {
    extern __shared__ char smem[];
    const uint32_t sb = smem_u32(smem);
    const uint32_t sWS = sb, sWD = sb + TILE_BYTES, sAB = sb + 2 * TILE_BYTES;
    const uint32_t sB1 = sb + 3 * TILE_BYTES;
    const int tid = threadIdx.x, w = tid >> 5, lane = tid & 31;
    const int lq = lane >> 2, lm = lane & 3, rg = w >> 2, cg = w & 3;

    load_weight(sWS, Ws, tid);
    load_weight(sWD, Wd, tid);
    if (tid < 128) ((float*)(smem + 3 * TILE_BYTES))[tid] = __ldg(b1 + tid);

    const int base = blockIdx.x * 128;
#pragma unroll
    for (int i = 0; i < 8; i++) {
        const int f4 = tid + 512 * i;
        const int row = f4 >> 5, c4 = f4 & 31;
        const int ng = base + row;
        const bool v = ng < N_NODES;
        float4 x = v ? __ldg((const float4*)(nfeat + (size_t)ng * 128) + c4)
                     : make_float4(0.f, 0.f, 0.f, 0.f);
        // fused nfeat passthrough (exact fp32 copy)
        if (v) *((float4*)(nfeat_out + (size_t)ng * 128) + c4) = x;
        sts128(adr(sAB, row, c4 * 4), tf32c(x.x), tf32c(x.y), tf32c(x.z), tf32c(x.w));
    }
    __syncthreads();

    const int Lb = 32 * cg + 8 * lm;                 // thread's logical col base
    const float4 bb0 = lds128f(sB1 + (uint32_t)Lb * 4);
    const float4 bb1 = lds128f(sB1 + (uint32_t)Lb * 4 + 16);

    float acc[32];
#pragma unroll
    for (int i = 0; i < 32; i++) acc[i] = 0.f;
    gemm512(sAB, sWS, rg, cg, lq, lm, acc);
#pragma unroll
    for (int mi = 0; mi < 2; mi++)
#pragma unroll
    for (int h = 0; h < 2; h++) {
        const int ng = base + 32 * rg + 16 * mi + 8 * h + lq;
        if (ng < N_NODES) {
            float4 o0, o1;
            o0.x = ACCJ(mi, h, 0) + bb0.x;  o0.y = ACCJ(mi, h, 1) + bb0.y;
            o0.z = ACCJ(mi, h, 2) + bb0.z;  o0.w = ACCJ(mi, h, 3) + bb0.w;
            o1.x = ACCJ(mi, h, 4) + bb1.x;  o1.y = ACCJ(mi, h, 5) + bb1.y;
            o1.z = ACCJ(mi, h, 6) + bb1.z;  o1.w = ACCJ(mi, h, 7) + bb1.w;
            float4* p = (float4*)(g_srcproj + (size_t)ng * 128 + Lb);
            p[0] = o0; p[1] = o1;
        }
    }

#pragma unroll
    for (int i = 0; i < 32; i++) acc[i] = 0.f;
    gemm512(sAB, sWD, rg, cg, lq, lm, acc);
#pragma unroll
    for (int mi = 0; mi < 2; mi++)
#pragma unroll
    for (int h = 0; h < 2; h++) {
        const int ng = base + 32 * rg + 16 * mi + 8 * h + lq;
        if (ng < N_NODES) {
            float4 o0, o1;
            o0.x = ACCJ(mi, h, 0);  o0.y = ACCJ(mi, h, 1);
            o0.z = ACCJ(mi, h, 2);  o0.w = ACCJ(mi, h, 3);
            o1.x = ACCJ(mi, h, 4);  o1.y = ACCJ(mi, h, 5);
            o1.z = ACCJ(mi, h, 6);  o1.w = ACCJ(mi, h, 7);
            float4* p = (float4*)(g_dstproj + (size_t)ng * 128 + Lb);
            p[0] = o0; p[1] = o1;
        }
    }
}

// ---------------- fused edge kernel (persistent, 512 thr) ----------------
// SMEM: We[0,67584) Wo[67584,135168) A[135168,202752) LN[202752,+4096)
//       bo gamma beta after
#define EDGE_SMEM 208384

// Prefetch one 128x128 fp32 tile of efeat into padded SMEM via cp.async.
DEVINL void prefetch_efeat(uint32_t sAB, const float* __restrict__ efeat,
                           int tile, int tid) {
    const int base = tile * 128;
#pragma unroll
    for (int i = 0; i < 8; i++) {
        const int f4 = tid + 512 * i;
        const int row = f4 >> 5, c4 = f4 & 31;
        const int e = base + row;
        const bool v = e < N_EDGES;
        const float* g = efeat + (size_t)(v ? e : 0) * 128 + c4 * 4;
        cpasync16(adr(sAB, row, c4 * 4), g, v ? 16 : 0);
    }
    cpcommit();
}

__global__ void __launch_bounds__(512, 1)
edge_kernel(const float* __restrict__ efeat, const int* __restrict__ src,
            const int* __restrict__ dst, const float* __restrict__ We,
            const float* __restrict__ Wo, const float* __restrict__ bo,
            const float* __restrict__ gamma, const float* __restrict__ beta,
            float* __restrict__ out) {
    extern __shared__ char smem[];
    const uint32_t sb = smem_u32(smem);
    const uint32_t sWE = sb, sWO = sb + TILE_BYTES, sAB = sb + 2 * TILE_BYTES;
    const uint32_t sLN = sb + 3 * TILE_BYTES;
    const uint32_t sBO = sLN + 4096, sGA = sBO + 512, sBE = sGA + 512;
    const int tid = threadIdx.x, w = tid >> 5, lane = tid & 31;
    const int lq = lane >> 2, lm = lane & 3, rg = w >> 2, cg = w & 3;

    load_weight(sWE, We, tid);
    load_weight(sWO, Wo, tid);
    if (tid < 128) {
        ((float*)(smem + (sBO - sb)))[tid] = __ldg(bo + tid);
        ((float*)(smem + (sGA - sb)))[tid] = __ldg(gamma + tid);
        ((float*)(smem + (sBE - sb)))[tid] = __ldg(beta + tid);
    }
    // prologue: prefetch first tile (raw fp32; tf32 mma truncates low bits)
    prefetch_efeat(sAB, efeat, blockIdx.x, tid);
    __syncthreads();

    const int Lb = 32 * cg + 8 * lm;                 // thread's logical col base
    const float4 bo0 = lds128f(sBO + (uint32_t)Lb * 4);
    const float4 bo1 = lds128f(sBO + (uint32_t)Lb * 4 + 16);
    const float4 ga0 = lds128f(sGA + (uint32_t)Lb * 4);
    const float4 ga1 = lds128f(sGA + (uint32_t)Lb * 4 + 16);
    const float4 be0 = lds128f(sBE + (uint32_t)Lb * 4);
    const float4 be1 = lds128f(sBE + (uint32_t)Lb * 4 + 16);

    for (int tile = blockIdx.x; tile < ETILES; tile += GRID_E) {
        const int base = tile * 128;
        cpwait0();
        __syncthreads();                      // (a) efeat tile ready in A

        // prefetch gather indices early (consumed after GEMM1)
        int si[4], di[4];
        bool vr[4];
#pragma unroll
        for (int mi = 0; mi < 2; mi++)
#pragma unroll
        for (int h = 0; h < 2; h++) {
            const int e = base + 32 * rg + 16 * mi + 8 * h + lq;
            const bool v = e < N_EDGES;
            vr[mi * 2 + h] = v;
            si[mi * 2 + h] = v ? __ldg(src + e) : 0;
            di[mi * 2 + h] = v ? __ldg(dst + e) : 0;
        }

        float acc[32];
#pragma unroll
        for (int i = 0; i < 32; i++) acc[i] = 0.f;
        gemm512(sAB, sWE, rg, cg, lq, lm, acc);   // h-pre = efeat @ We^T
        __syncthreads();                      // (c) all warps done reading A

        // epilogue1: + srcproj[src] (b1 folded) + dstproj[dst], SiLU, act -> A
#pragma unroll
        for (int mi = 0; mi < 2; mi++)
#pragma unroll
        for (int h = 0; h < 2; h++) {
            const int R = 32 * rg + 16 * mi + 8 * h + lq;
            const float4* ps = (const float4*)(g_srcproj + (size_t)si[mi * 2 + h] * 128 + Lb);
            const float4* pd = (const float4*)(g_dstproj + (size_t)di[mi * 2 + h] * 128 + Lb);
            float4 s0 = __ldg(ps), s1 = __ldg(ps + 1);
            float4 d0 = __ldg(pd), d1 = __ldg(pd + 1);
            float x0 = silu_f(ACCJ(mi, h, 0) + s0.x + d0.x);
            float x1 = silu_f(ACCJ(mi, h, 1) + s0.y + d0.y);
            float x2 = silu_f(ACCJ(mi, h, 2) + s0.z + d0.z);
            float x3 = silu_f(ACCJ(mi, h, 3) + s0.w + d0.w);
            float x4 = silu_f(ACCJ(mi, h, 4) + s1.x + d1.x);
            float x5 = silu_f(ACCJ(mi, h, 5) + s1.y + d1.y);
            float x6 = silu_f(ACCJ(mi, h, 6) + s1.z + d1.z);
            float x7 = silu_f(ACCJ(mi, h, 7) + s1.w + d1.w);
            sts128(adr(sAB, R, Lb),     tf32c(x0), tf32c(x1), tf32c(x2), tf32c(x3));
            sts128(adr(sAB, R, Lb + 4), tf32c(x4), tf32c(x5), tf32c(x6), tf32c(x7));
        }
        __syncthreads();                      // (d) act tile complete

#pragma unroll
        for (int i = 0; i < 32; i++) acc[i] = 0.f;
        gemm512(sAB, sWO, rg, cg, lq, lm, acc);   // o-pre = act @ Wo^T

        // epilogue2a: + bo, LayerNorm partials (quad shfl + cross-warp SMEM)
#pragma unroll
        for (int mi = 0; mi < 2; mi++)
#pragma unroll
        for (int h = 0; h < 2; h++) {
            float s = 0.f, q = 0.f;
#pragma unroll
            for (int j = 0; j < 8; j++) {
                const float b = (j < 4) ? ((const float*)&bo0)[j] : ((const float*)&bo1)[j - 4];
                float x = ACCJ(mi, h, j) + b;
                ACCJ(mi, h, j) = x;
                s += x;
                q += x * x;
            }
            s += __shfl_xor_sync(0xffffffffu, s, 1);
            q += __shfl_xor_sync(0xffffffffu, q, 1);
            s += __shfl_xor_sync(0xffffffffu, s, 2);
            q += __shfl_xor_sync(0xffffffffu, q, 2);
            if (lm == 0) {
                const int R = 32 * rg + 16 * mi + 8 * h + lq;
                sts64f(sLN + (uint32_t)(cg * 128 + R) * 8, s, q);
            }
        }
        __syncthreads();                      // (e) LN partials visible; A free

        // prefetch next tile's efeat into A (overlaps epilogue2b)
        if (tile + GRID_E < ETILES)
            prefetch_efeat(sAB, efeat, tile + GRID_E, tid);

        // epilogue2b: normalize, affine, + residual efeat (L2-hot), store
#pragma unroll
        for (int mi = 0; mi < 2; mi++)
#pragma unroll
        for (int h = 0; h < 2; h++) {
            const int R = 32 * rg + 16 * mi + 8 * h + lq;
            const int e = base + R;
            const bool v = vr[mi * 2 + h];
            float2 p0 = *(float2*)(smem + (sLN - sb) + (uint32_t)R * 8);
            float2 p1 = *(float2*)(smem + (sLN - sb) + (uint32_t)(128 + R) * 8);
            float2 p2 = *(float2*)(smem + (sLN - sb) + (uint32_t)(256 + R) * 8);
            float2 p3 = *(float2*)(smem + (sLN - sb) + (uint32_t)(384 + R) * 8);
            const float mu  = (p0.x + p1.x + p2.x + p3.x) * 0.0078125f;
            const float var = (p0.y + p1.y + p2.y + p3.y) * 0.0078125f - mu * mu;
            const float rs  = rsqrtf(var + 1e-5f);
            const float4* pe = (const float4*)(efeat + (size_t)(v ? e : 0) * 128 + Lb);
            float4 r0 = v ? __ldg(pe)     : make_float4(0.f, 0.f, 0.f, 0.f);
            float4 r1 = v ? __ldg(pe + 1) : make_float4(0.f, 0.f, 0.f, 0.f);
            float4 o0, o1;
            o0.x = (ACCJ(mi, h, 0) - mu) * rs * ga0.x + be0.x + r0.x;
            o0.y = (ACCJ(mi, h, 1) - mu) * rs * ga0.y + be0.y + r0.y;
            o0.z = (ACCJ(mi, h, 2) - mu) * rs * ga0.z + be0.z + r0.z;
            o0.w = (ACCJ(mi, h, 3) - mu) * rs * ga0.w + be0.w + r0.w;
            o1.x = (ACCJ(mi, h, 4) - mu) * rs * ga1.x + be1.x + r1.x;
            o1.y = (ACCJ(mi, h, 5) - mu) * rs * ga1.y + be1.y + r1.y;
            o1.z = (ACCJ(mi, h, 6) - mu) * rs * ga1.z + be1.z + r1.z;
            o1.w = (ACCJ(mi, h, 7) - mu) * rs * ga1.w + be1.w + r1.w;
            if (v) {
                float4* po = (float4*)(out + (size_t)e * 128 + Lb);
                po[0] = o0; po[1] = o1;
            }
        }
    }
}

// ---------------- launch ----------------

extern "C" void kernel_launch(void* const* d_in, const int* in_sizes, int n_in,
                              void* d_out, int out_size) {
    const float* efeat = (const float*)d_in[0];
    const float* nfeat = (const float*)d_in[1];
    const int*   src   = (const int*)d_in[2];
    const int*   dst   = (const int*)d_in[3];
    const float* We    = (const float*)d_in[4];
    const float* Ws    = (const float*)d_in[5];
    const float* Wd    = (const float*)d_in[6];
    const float* b1    = (const float*)d_in[7];
    const float* Wo    = (const float*)d_in[8];
    const float* bo    = (const float*)d_in[9];
    const float* gamma = (const float*)d_in[10];
    const float* beta  = (const float*)d_in[11];
    float* out = (float*)d_out;

    cudaFuncSetAttribute(node_kernel, cudaFuncAttributeMaxDynamicSharedMemorySize, NODE_SMEM);
    cudaFuncSetAttribute(edge_kernel, cudaFuncAttributeMaxDynamicSharedMemorySize, EDGE_SMEM);

    // node kernel also writes the nfeat passthrough output
    node_kernel<<<NTILES, 512, NODE_SMEM>>>(nfeat, Ws, Wd, b1,
                                            out + (size_t)N_EDGES * 128);
    edge_kernel<<<GRID_E, 512, EDGE_SMEM>>>(efeat, src, dst, We, Wo, bo, gamma, beta, out);
}

// round 11
// speedup vs baseline: 1.2701x; 1.0371x over previous
#include <cuda_runtime.h>
#include <cstdint>

#define DEVINL static __device__ __forceinline__

#define N_EDGES 600000
#define N_NODES 50000
#define ETILES 4688     // ceil(600000/128)
#define NTILES 391      // ceil(50000/128)
#define GRID_E 148

// Padded tile geometry: 128 rows x 128 cols fp32, row stride 528B (132 floats).
// 132 mod 32 = 4  =>  bank(r*132 + lm) = (4*lq + lm + c) mod 32 over the warp's
// (lq,lm) grid -> ALL 32 LANES DISTINCT banks for the mma access pattern, with
// addresses LINEAR in k/mi/nt (LDS immediates, 2 base regs per GEMM).
#define RSTRIDE 528
#define TILE_BYTES (128 * RSTRIDE)   // 67584

// Node projection scratch (b1 folded into srcproj). Static device mem (no allocs).
static __device__ float g_srcproj[(size_t)N_NODES * 128];
static __device__ float g_dstproj[(size_t)N_NODES * 128];

// ---------------- helpers ----------------

DEVINL uint32_t smem_u32(const void* p) {
    uint32_t a;
    asm("{ .reg .u64 t; cvta.to.shared.u64 t, %1; cvt.u32.u64 %0, t; }" : "=r"(a) : "l"(p));
    return a;
}
DEVINL uint32_t tf32c(float f) {
    uint32_t r;
    asm("cvt.rna.tf32.f32 %0, %1;" : "=r"(r) : "f"(f));
    return r;
}
DEVINL uint32_t lds32(uint32_t a) {
    uint32_t v;
    asm volatile("ld.shared.b32 %0, [%1];" : "=r"(v) : "r"(a));
    return v;
}
DEVINL float4 lds128f(uint32_t a) {
    float4 v;
    asm volatile("ld.shared.v4.f32 {%0,%1,%2,%3}, [%4];"
                 : "=f"(v.x), "=f"(v.y), "=f"(v.z), "=f"(v.w) : "r"(a));
    return v;
}
DEVINL void sts64f(uint32_t a, float x, float y) {
    asm volatile("st.shared.v2.f32 [%0], {%1,%2};" :: "r"(a), "f"(x), "f"(y));
}
DEVINL void sts128(uint32_t a, uint32_t x, uint32_t y, uint32_t z, uint32_t w) {
    asm volatile("st.shared.v4.b32 [%0], {%1,%2,%3,%4};" :: "r"(a), "r"(x), "r"(y), "r"(z), "r"(w));
}
DEVINL void cpasync16(uint32_t s, const void* g, int srcbytes) {
    asm volatile("cp.async.cg.shared.global [%0], [%1], 16, %2;"
                 :: "r"(s), "l"(g), "r"(srcbytes));
}
DEVINL void cpcommit() { asm volatile("cp.async.commit_group;" ::: "memory"); }
DEVINL void cpwait0()  { asm volatile("cp.async.wait_group 0;" ::: "memory"); }

// mbarrier-based group sync (sm_90-base PTX; avoids BAR hardware entirely,
// which faulted under concurrent different-id named barriers in R9/R10).
// Pattern: all 128 group threads arrive (release-cta), then spin on
// try_wait.parity (acquire-cta). Each barrier is used once per tile, so the
// parity bit is simply (iteration & 1), shared by all 16 barriers.
DEVINL void mbar_init(uint32_t a, uint32_t cnt) {
    asm volatile("mbarrier.init.shared.b64 [%0], %1;" :: "r"(a), "r"(cnt) : "memory");
}
DEVINL void gsync(uint32_t mb, uint32_t ph) {
    asm volatile(
        "{\n\t.reg .pred P;\n\t"
        "mbarrier.arrive.shared.b64 _, [%0];\n\t"
        "LW%=:\n\t"
        "mbarrier.try_wait.parity.acquire.cta.shared::cta.b64 P, [%0], %1, 0x989680;\n\t"
        "@P bra.uni LD%=;\n\t"
        "bra.uni LW%=;\n\t"
        "LD%=:\n\t}"
        :: "r"(mb), "r"(ph) : "memory");
}

// silu(x) = x*sigmoid(x) = h + h*tanh(h), h = x/2  (1 MUFU)
DEVINL float silu_f(float x) {
    float h = 0.5f * x, t;
    asm("tanh.approx.f32 %0, %1;" : "=f"(t) : "f"(h));
    return fmaf(h, t, h);
}

// Out-dim permutation: n = 32c+8a+2b+e -> 32c+8b+2a+e  (swap 2-bit fields a,b).
// Applied to weight SMEM rows so that a thread's D-fragment columns are the
// CONTIGUOUS logical columns 32*cg + 8*lm + {0..7}.
DEVINL int permn(int n) {
    return (n & 0x61) | ((n & 6) << 2) | ((n >> 2) & 6);
}

// Padded-tile address of element (row r, float-col c).
DEVINL uint32_t adr(uint32_t b, int r, int c) {
    return b + (uint32_t)r * (uint32_t)RSTRIDE + (uint32_t)c * 4u;
}

// m16n8k8 tf32 HMMA (base-target PTX)
DEVINL void mma8(float* d, const uint32_t* a, uint32_t b0, uint32_t b1) {
    asm volatile(
        "mma.sync.aligned.m16n8k8.row.col.f32.tf32.tf32.f32 "
        "{%0,%1,%2,%3}, {%4,%5,%6,%7}, {%8,%9}, {%0,%1,%2,%3};"
        : "+f"(d[0]), "+f"(d[1]), "+f"(d[2]), "+f"(d[3])
        : "r"(a[0]), "r"(a[1]), "r"(a[2]), "r"(a[3]), "r"(b0), "r"(b1));
}

// Load [128 out][128 in] row-major weight into padded SMEM (out-rows permuted).
DEVINL void load_weight(uint32_t sbW, const float* __restrict__ W, int tid) {
#pragma unroll 1
    for (int i = tid; i < 4096; i += 512) {
        int n = i >> 5, k4 = (i & 31) << 2;
        float4 v = __ldg((const float4*)W + i);
        sts128(adr(sbW, permn(n), k4), tf32c(v.x), tf32c(v.y), tf32c(v.z), tf32c(v.w));
    }
}

// 128x128x128 GEMM, 16 warps. Warp w: rg=w>>2 rows [32rg,+32), cg=w&3 cols [32cg,+32).
// acc[(mi*4+nt)*4 + 2*h + e]; logical col of (nt,e) = 32cg + 8lm + 2nt + e.
// All load addresses are base + compile-time immediates (2 base regs total).
DEVINL void gemm512(uint32_t sbA, uint32_t sbW, int rg, int cg, int lq, int lm,
                    float acc[32]) {
    const uint32_t bA = sbA + (uint32_t)(32 * rg + lq) * RSTRIDE + 4u * lm;
    const uint32_t bB = sbW + (uint32_t)(32 * cg + lq) * RSTRIDE + 4u * lm;
#pragma unroll
    for (int kk = 0; kk < 16; kk++) {
        uint32_t a[2][4];
#pragma unroll
        for (int mi = 0; mi < 2; mi++) {
            const uint32_t r = bA + (uint32_t)(mi * 16 * RSTRIDE + kk * 32);
            a[mi][0] = lds32(r);
            a[mi][1] = lds32(r + 8 * RSTRIDE);
            a[mi][2] = lds32(r + 16);
            a[mi][3] = lds32(r + 8 * RSTRIDE + 16);
        }
#pragma unroll
        for (int nt = 0; nt < 4; nt++) {
            const uint32_t rb = bB + (uint32_t)(nt * 8 * RSTRIDE + kk * 32);
            uint32_t b0 = lds32(rb);
            uint32_t b1 = lds32(rb + 16);
            mma8(acc + nt * 4,      a[0], b0, b1);
            mma8(acc + 16 + nt * 4, a[1], b0, b1);
        }
    }
}

// Extract thread's 8 contiguous logical cols (j = 2*nt+e) for row-rep (mi,h).
#define ACCJ(mi, h, j) acc[((mi) * 4 + ((j) >> 1)) * 4 + 2 * (h) + ((j) & 1)]

// ---------------- node projection kernel ----------------
// SMEM: Ws[0,67584) Wd[67584,135168) A[135168,202752) b1[202752,+512)
#define NODE_SMEM 203264

__global__ void __launch_bounds__(512, 1)
node_kernel(const float* __restrict__ nfeat, const float* __restrict__ Ws,
            const float* __restrict__ Wd, const float* __restrict__ b1,
            float* __restrict__ nfeat_out) {
    extern __shared__ char smem[];
    const uint32_t sb = smem_u32(smem);
    const uint32_t sWS = sb, sWD = sb + TILE_BYTES, sAB = sb + 2 * TILE_BYTES;
    const uint32_t sB1 = sb + 3 * TILE_BYTES;
    const int tid = threadIdx.x, w = tid >> 5, lane = tid & 31;
    const int lq = lane >> 2, lm = lane & 3, rg = w >> 2, cg = w & 3;

    load_weight(sWS, Ws, tid);
    load_weight(sWD, Wd, tid);
    if (tid < 128) ((float*)(smem + 3 * TILE_BYTES))[tid] = __ldg(b1 + tid);

    const int base = blockIdx.x * 128;
#pragma unroll
    for (int i = 0; i < 8; i++) {
        const int f4 = tid + 512 * i;
        const int row = f4 >> 5, c4 = f4 & 31;
        const int ng = base + row;
        const bool v = ng < N_NODES;
        float4 x = v ? __ldg((const float4*)(nfeat + (size_t)ng * 128) + c4)
                     : make_float4(0.f, 0.f, 0.f, 0.f);
        // fused nfeat passthrough (exact fp32 copy)
        if (v) *((float4*)(nfeat_out + (size_t)ng * 128) + c4) = x;
        sts128(adr(sAB, row, c4 * 4), tf32c(x.x), tf32c(x.y), tf32c(x.z), tf32c(x.w));
    }
    __syncthreads();

    const int Lb = 32 * cg + 8 * lm;                 // thread's logical col base
    const float4 bb0 = lds128f(sB1 + (uint32_t)Lb * 4);
    const float4 bb1 = lds128f(sB1 + (uint32_t)Lb * 4 + 16);

    float acc[32];
#pragma unroll
    for (int i = 0; i < 32; i++) acc[i] = 0.f;
    gemm512(sAB, sWS, rg, cg, lq, lm, acc);
#pragma unroll
    for (int mi = 0; mi < 2; mi++)
#pragma unroll
    for (int h = 0; h < 2; h++) {
        const int ng = base + 32 * rg + 16 * mi + 8 * h + lq;
        if (ng < N_NODES) {
            float4 o0, o1;
            o0.x = ACCJ(mi, h, 0) + bb0.x;  o0.y = ACCJ(mi, h, 1) + bb0.y;
            o0.z = ACCJ(mi, h, 2) + bb0.z;  o0.w = ACCJ(mi, h, 3) + bb0.w;
            o1.x = ACCJ(mi, h, 4) + bb1.x;  o1.y = ACCJ(mi, h, 5) + bb1.y;
            o1.z = ACCJ(mi, h, 6) + bb1.z;  o1.w = ACCJ(mi, h, 7) + bb1.w;
            float4* p = (float4*)(g_srcproj + (size_t)ng * 128 + Lb);
            p[0] = o0; p[1] = o1;
        }
    }

#pragma unroll
    for (int i = 0; i < 32; i++) acc[i] = 0.f;
    gemm512(sAB, sWD, rg, cg, lq, lm, acc);
#pragma unroll
    for (int mi = 0; mi < 2; mi++)
#pragma unroll
    for (int h = 0; h < 2; h++) {
        const int ng = base + 32 * rg + 16 * mi + 8 * h + lq;
        if (ng < N_NODES) {
            float4 o0, o1;
            o0.x = ACCJ(mi, h, 0);  o0.y = ACCJ(mi, h, 1);
            o0.z = ACCJ(mi, h, 2);  o0.w = ACCJ(mi, h, 3);
            o1.x = ACCJ(mi, h, 4);  o1.y = ACCJ(mi, h, 5);
            o1.z = ACCJ(mi, h, 6);  o1.w = ACCJ(mi, h, 7);
            float4* p = (float4*)(g_dstproj + (size_t)ng * 128 + Lb);
            p[0] = o0; p[1] = o1;
        }
    }
}

// ---------------- fused edge kernel (persistent, 512 thr) ----------------
// SMEM: We[0,67584) Wo[67584,135168) A[135168,202752) LN[202752,+4096)
//       bo@206848 gamma@207360 beta@207872 mbarriers@208384 (16 x 8B)
#define EDGE_SMEM 208512

// Group-local prefetch: each rg-group (128 threads) fills ONLY its own 32 rows
// [32rg, 32rg+32) of the A tile, so the fill is ordered by the group's barrier
// rather than a block-wide one.
DEVINL void prefetch_efeat_grp(uint32_t sAB, const float* __restrict__ efeat,
                               int tile, int rg, int gt) {
    const int base = tile * 128 + 32 * rg;
#pragma unroll
    for (int i = 0; i < 8; i++) {
        const int f4 = gt + 128 * i;                 // 0..1023 within group
        const int row = f4 >> 5, c4 = f4 & 31;       // row 0..31, col4 0..31
        const int e = base + row;
        const bool v = e < N_EDGES;
        const float* g = efeat + (size_t)(v ? e : 0) * 128 + c4 * 4;
        cpasync16(adr(sAB, 32 * rg + row, c4 * 4), g, v ? 16 : 0);
    }
    cpcommit();
}

__global__ void __launch_bounds__(512, 1)
edge_kernel(const float* __restrict__ efeat, const int* __restrict__ src,
            const int* __restrict__ dst, const float* __restrict__ We,
            const float* __restrict__ Wo, const float* __restrict__ bo,
            const float* __restrict__ gamma, const float* __restrict__ beta,
            float* __restrict__ out) {
    extern __shared__ char smem[];
    const uint32_t sb = smem_u32(smem);
    const uint32_t sWE = sb, sWO = sb + TILE_BYTES, sAB = sb + 2 * TILE_BYTES;
    const uint32_t sLN = sb + 3 * TILE_BYTES;
    const uint32_t sBO = sLN + 4096, sGA = sBO + 512, sBE = sGA + 512;
    const uint32_t sMB = sBE + 512;                  // 16 mbarriers (4 grp x 4 pts)
    const int tid = threadIdx.x, w = tid >> 5, lane = tid & 31;
    const int lq = lane >> 2, lm = lane & 3, rg = w >> 2, cg = w & 3;
    const int gt = tid & 127;                        // thread id within rg-group
    const uint32_t mb0 = sMB + (uint32_t)rg * 32u;   // this group's 4 barriers

    load_weight(sWE, We, tid);
    load_weight(sWO, Wo, tid);
    if (tid < 128) {
        ((float*)(smem + (sBO - sb)))[tid] = __ldg(bo + tid);
        ((float*)(smem + (sGA - sb)))[tid] = __ldg(gamma + tid);
        ((float*)(smem + (sBE - sb)))[tid] = __ldg(beta + tid);
    }
    if (tid < 16) mbar_init(sMB + (uint32_t)tid * 8u, 128);
    // prologue: prefetch first tile (raw fp32; tf32 mma truncates low bits)
    prefetch_efeat_grp(sAB, efeat, blockIdx.x, rg, gt);
    __syncthreads();      // weights/biases/mbarriers visible; groups decouple after

    const int Lb = 32 * cg + 8 * lm;                 // thread's logical col base
    const float4 bo0 = lds128f(sBO + (uint32_t)Lb * 4);
    const float4 bo1 = lds128f(sBO + (uint32_t)Lb * 4 + 16);
    const float4 ga0 = lds128f(sGA + (uint32_t)Lb * 4);
    const float4 ga1 = lds128f(sGA + (uint32_t)Lb * 4 + 16);
    const float4 be0 = lds128f(sBE + (uint32_t)Lb * 4);
    const float4 be1 = lds128f(sBE + (uint32_t)Lb * 4 + 16);

    uint32_t ph = 0;                                 // shared parity for all 4 pts

    for (int tile = blockIdx.x; tile < ETILES; tile += GRID_E) {
        const int base = tile * 128;
        cpwait0();
        gsync(mb0 + 0, ph);                   // (a) group's 32 A rows ready

        // prefetch gather indices early (consumed after GEMM1)
        int si[4], di[4];
        bool vr[4];
#pragma unroll
        for (int mi = 0; mi < 2; mi++)
#pragma unroll
        for (int h = 0; h < 2; h++) {
            const int e = base + 32 * rg + 16 * mi + 8 * h + lq;
            const bool v = e < N_EDGES;
            vr[mi * 2 + h] = v;
            si[mi * 2 + h] = v ? __ldg(src + e) : 0;
            di[mi * 2 + h] = v ? __ldg(dst + e) : 0;
        }

        float acc[32];
#pragma unroll
        for (int i = 0; i < 32; i++) acc[i] = 0.f;
        gemm512(sAB, sWE, rg, cg, lq, lm, acc);   // h-pre = efeat @ We^T
        gsync(mb0 + 8, ph);                   // (c) group done reading its A rows

        // epilogue1: + srcproj[src] (b1 folded) + dstproj[dst], SiLU, act -> A
#pragma unroll
        for (int mi = 0; mi < 2; mi++)
#pragma unroll
        for (int h = 0; h < 2; h++) {
            const int R = 32 * rg + 16 * mi + 8 * h + lq;
            const float4* ps = (const float4*)(g_srcproj + (size_t)si[mi * 2 + h] * 128 + Lb);
            const float4* pd = (const float4*)(g_dstproj + (size_t)di[mi * 2 + h] * 128 + Lb);
            float4 s0 = __ldg(ps), s1 = __ldg(ps + 1);
            float4 d0 = __ldg(pd), d1 = __ldg(pd + 1);
            float x0 = silu_f(ACCJ(mi, h, 0) + s0.x + d0.x);
            float x1 = silu_f(ACCJ(mi, h, 1) + s0.y + d0.y);
            float x2 = silu_f(ACCJ(mi, h, 2) + s0.z + d0.z);
            float x3 = silu_f(ACCJ(mi, h, 3) + s0.w + d0.w);
            float x4 = silu_f(ACCJ(mi, h, 4) + s1.x + d1.x);
            float x5 = silu_f(ACCJ(mi, h, 5) + s1.y + d1.y);
            float x6 = silu_f(ACCJ(mi, h, 6) + s1.z + d1.z);
            float x7 = silu_f(ACCJ(mi, h, 7) + s1.w + d1.w);
            sts128(adr(sAB, R, Lb),     tf32c(x0), tf32c(x1), tf32c(x2), tf32c(x3));
            sts128(adr(sAB, R, Lb + 4), tf32c(x4), tf32c(x5), tf32c(x6), tf32c(x7));
        }
        gsync(mb0 + 16, ph);                  // (d) group's act rows complete

#pragma unroll
        for (int i = 0; i < 32; i++) acc[i] = 0.f;
        gemm512(sAB, sWO, rg, cg, lq, lm, acc);   // o-pre = act @ Wo^T

        // epilogue2a: + bo, LayerNorm partials (quad shfl + cross-warp SMEM)
#pragma unroll
        for (int mi = 0; mi < 2; mi++)
#pragma unroll
        for (int h = 0; h < 2; h++) {
            float s = 0.f, q = 0.f;
#pragma unroll
            for (int j = 0; j < 8; j++) {
                const float b = (j < 4) ? ((const float*)&bo0)[j] : ((const float*)&bo1)[j - 4];
                float x = ACCJ(mi, h, j) + b;
                ACCJ(mi, h, j) = x;
                s += x;
                q += x * x;
            }
            s += __shfl_xor_sync(0xffffffffu, s, 1);
            q += __shfl_xor_sync(0xffffffffu, q, 1);
            s += __shfl_xor_sync(0xffffffffu, s, 2);
            q += __shfl_xor_sync(0xffffffffu, q, 2);
            if (lm == 0) {
                const int R = 32 * rg + 16 * mi + 8 * h + lq;
                sts64f(sLN + (uint32_t)(cg * 128 + R) * 8, s, q);
            }
        }
        gsync(mb0 + 24, ph);                  // (e) LN partials visible; A rows free

        // prefetch next tile's efeat into group's A rows (overlaps epilogue2b)
        if (tile + GRID_E < ETILES)
            prefetch_efeat_grp(sAB, efeat, tile + GRID_E, rg, gt);

        // epilogue2b: normalize, affine, + residual efeat (L2-hot), store
#pragma unroll
        for (int mi = 0; mi < 2; mi++)
#pragma unroll
        for (int h = 0; h < 2; h++) {
            const int R = 32 * rg + 16 * mi + 8 * h + lq;
            const int e = base + R;
            const bool v = vr[mi * 2 + h];
            float2 p0 = *(float2*)(smem + (sLN - sb) + (uint32_t)R * 8);
            float2 p1 = *(float2*)(smem + (sLN - sb) + (uint32_t)(128 + R) * 8);
            float2 p2 = *(float2*)(smem + (sLN - sb) + (uint32_t)(256 + R) * 8);
            float2 p3 = *(float2*)(smem + (sLN - sb) + (uint32_t)(384 + R) * 8);
            const float mu  = (p0.x + p1.x + p2.x + p3.x) * 0.0078125f;
            const float var = (p0.y + p1.y + p2.y + p3.y) * 0.0078125f - mu * mu;
            const float rs  = rsqrtf(var + 1e-5f);
            const float4* pe = (const float4*)(efeat + (size_t)(v ? e : 0) * 128 + Lb);
            float4 r0 = v ? __ldg(pe)     : make_float4(0.f, 0.f, 0.f, 0.f);
            float4 r1 = v ? __ldg(pe + 1) : make_float4(0.f, 0.f, 0.f, 0.f);
            float4 o0, o1;
            o0.x = (ACCJ(mi, h, 0) - mu) * rs * ga0.x + be0.x + r0.x;
            o0.y = (ACCJ(mi, h, 1) - mu) * rs * ga0.y + be0.y + r0.y;
            o0.z = (ACCJ(mi, h, 2) - mu) * rs * ga0.z + be0.z + r0.z;
            o0.w = (ACCJ(mi, h, 3) - mu) * rs * ga0.w + be0.w + r0.w;
            o1.x = (ACCJ(mi, h, 4) - mu) * rs * ga1.x + be1.x + r1.x;
            o1.y = (ACCJ(mi, h, 5) - mu) * rs * ga1.y + be1.y + r1.y;
            o1.z = (ACCJ(mi, h, 6) - mu) * rs * ga1.z + be1.z + r1.z;
            o1.w = (ACCJ(mi, h, 7) - mu) * rs * ga1.w + be1.w + r1.w;
            if (v) {
                float4* po = (float4*)(out + (size_t)e * 128 + Lb);
                po[0] = o0; po[1] = o1;
            }
        }
        ph ^= 1;                              // all 4 barriers used once per tile
    }
}

// ---------------- launch ----------------

extern "C" void kernel_launch(void* const* d_in, const int* in_sizes, int n_in,
                              void* d_out, int out_size) {
    const float* efeat = (const float*)d_in[0];
    const float* nfeat = (const float*)d_in[1];
    const int*   src   = (const int*)d_in[2];
    const int*   dst   = (const int*)d_in[3];
    const float* We    = (const float*)d_in[4];
    const float* Ws    = (const float*)d_in[5];
    const float* Wd    = (const float*)d_in[6];
    const float* b1    = (const float*)d_in[7];
    const float* Wo    = (const float*)d_in[8];
    const float* bo    = (const float*)d_in[9];
    const float* gamma = (const float*)d_in[10];
    const float* beta  = (const float*)d_in[11];
    float* out = (float*)d_out;

    cudaFuncSetAttribute(node_kernel, cudaFuncAttributeMaxDynamicSharedMemorySize, NODE_SMEM);
    cudaFuncSetAttribute(edge_kernel, cudaFuncAttributeMaxDynamicSharedMemorySize, EDGE_SMEM);

    // node kernel also writes the nfeat passthrough output
    node_kernel<<<NTILES, 512, NODE_SMEM>>>(nfeat, Ws, Wd, b1,
                                            out + (size_t)N_EDGES * 128);
    edge_kernel<<<GRID_E, 512, EDGE_SMEM>>>(efeat, src, dst, We, Wo, bo, gamma, beta, out);
}

// round 12
// speedup vs baseline: 1.6534x; 1.3018x over previous
#include <cuda_runtime.h>
#include <cstdint>

#define DEVINL static __device__ __forceinline__

#define N_EDGES 600000
#define N_NODES 50000
#define ETILES 4688     // ceil(600000/128)
#define NTILES 391      // ceil(50000/128)
#define GRID_E 148

// fp16 tile geometry: 128 rows x 128 cols, row stride 272B (136 halfs).
// 272/4 = 68 ≡ 4 (mod 32) => 4B-bank(r*272 + 4*lm + imm) = (4*lq + lm + c) mod 32
// over the warp's (lq,lm) grid -> all 32 lanes distinct banks for the mma
// fragment pattern, with addresses LINEAR in k/mi/nt (LDS immediates).
#define RS16 272
#define T16_BYTES (128 * RS16)      // 34816
// fp32 staging tile for cp.async efeat prefetch (plain 512B rows).
#define RSTG 512
#define STG_BYTES (128 * RSTG)      // 65536

// Node projection scratch (b1 folded into srcproj). Static device mem (no allocs).
static __device__ float g_srcproj[(size_t)N_NODES * 128];
static __device__ float g_dstproj[(size_t)N_NODES * 128];

// ---------------- helpers ----------------

DEVINL uint32_t smem_u32(const void* p) {
    uint32_t a;
    asm("{ .reg .u64 t; cvta.to.shared.u64 t, %1; cvt.u32.u64 %0, t; }" : "=r"(a) : "l"(p));
    return a;
}
// pack two f32 -> f16x2 {lo, hi} (first PTX src = high half)
DEVINL uint32_t packh2(float lo, float hi) {
    uint32_t r;
    asm("cvt.rn.f16x2.f32 %0, %1, %2;" : "=r"(r) : "f"(hi), "f"(lo));
    return r;
}
DEVINL uint32_t lds32(uint32_t a) {
    uint32_t v;
    asm volatile("ld.shared.b32 %0, [%1];" : "=r"(v) : "r"(a));
    return v;
}
DEVINL float4 lds128f(uint32_t a) {
    float4 v;
    asm volatile("ld.shared.v4.f32 {%0,%1,%2,%3}, [%4];"
                 : "=f"(v.x), "=f"(v.y), "=f"(v.z), "=f"(v.w) : "r"(a));
    return v;
}
DEVINL void sts64f(uint32_t a, float x, float y) {
    asm volatile("st.shared.v2.f32 [%0], {%1,%2};" :: "r"(a), "f"(x), "f"(y));
}
DEVINL void sts64(uint32_t a, uint32_t x, uint32_t y) {
    asm volatile("st.shared.v2.b32 [%0], {%1,%2};" :: "r"(a), "r"(x), "r"(y));
}
DEVINL void sts128(uint32_t a, uint32_t x, uint32_t y, uint32_t z, uint32_t w) {
    asm volatile("st.shared.v4.b32 [%0], {%1,%2,%3,%4};" :: "r"(a), "r"(x), "r"(y), "r"(z), "r"(w));
}
DEVINL void cpasync16(uint32_t s, const void* g, int srcbytes) {
    asm volatile("cp.async.cg.shared.global [%0], [%1], 16, %2;"
                 :: "r"(s), "l"(g), "r"(srcbytes));
}
DEVINL void cpcommit() { asm volatile("cp.async.commit_group;" ::: "memory"); }
DEVINL void cpwait0()  { asm volatile("cp.async.wait_group 0;" ::: "memory"); }

// mbarrier-based group sync (R11 win; avoids BAR hw, which faulted in R9/R10).
DEVINL void mbar_init(uint32_t a, uint32_t cnt) {
    asm volatile("mbarrier.init.shared.b64 [%0], %1;" :: "r"(a), "r"(cnt) : "memory");
}
DEVINL void gsync(uint32_t mb, uint32_t ph) {
    asm volatile(
        "{\n\t.reg .pred P;\n\t"
        "mbarrier.arrive.shared.b64 _, [%0];\n\t"
        "LW%=:\n\t"
        "mbarrier.try_wait.parity.acquire.cta.shared::cta.b64 P, [%0], %1, 0x989680;\n\t"
        "@P bra.uni LD%=;\n\t"
        "bra.uni LW%=;\n\t"
        "LD%=:\n\t}"
        :: "r"(mb), "r"(ph) : "memory");
}

// silu(x) = x*sigmoid(x) = h + h*tanh(h), h = x/2  (1 MUFU)
DEVINL float silu_f(float x) {
    float h = 0.5f * x, t;
    asm("tanh.approx.f32 %0, %1;" : "=f"(t) : "f"(h));
    return fmaf(h, t, h);
}

// Out-dim permutation: n = 32c+8a+2b+e -> 32c+8b+2a+e  (swap 2-bit fields).
// Thread's D-fragment columns become CONTIGUOUS logical cols 32*cg+8*lm+{0..7}.
// (m16n8k16 D layout == m16n8k8 D layout, so all epilogue logic is unchanged.)
DEVINL int permn(int n) {
    return (n & 0x61) | ((n & 6) << 2) | ((n >> 2) & 6);
}

// fp16 tile address: row r, BYTE column cb.
DEVINL uint32_t adr16(uint32_t b, int r, int cb) {
    return b + (uint32_t)r * (uint32_t)RS16 + (uint32_t)cb;
}

// m16n8k16 fp16 HMMA, fp32 accum (base-target PTX, sm_80+)
DEVINL void mma16(float* d, const uint32_t* a, uint32_t b0, uint32_t b1) {
    asm volatile(
        "mma.sync.aligned.m16n8k16.row.col.f32.f16.f16.f32 "
        "{%0,%1,%2,%3}, {%4,%5,%6,%7}, {%8,%9}, {%0,%1,%2,%3};"
        : "+f"(d[0]), "+f"(d[1]), "+f"(d[2]), "+f"(d[3])
        : "r"(a[0]), "r"(a[1]), "r"(a[2]), "r"(a[3]), "r"(b0), "r"(b1));
}

// Load [128 out][128 in] row-major fp32 weight into fp16 SMEM (out-rows permuted).
DEVINL void load_weight16(uint32_t sbW, const float* __restrict__ W, int tid) {
#pragma unroll 1
    for (int i = tid; i < 4096; i += 512) {
        int n = i >> 5, k4 = (i & 31) << 2;      // k4 = starting k index
        float4 v = __ldg((const float4*)W + i);
        sts64(adr16(sbW, permn(n), k4 * 2), packh2(v.x, v.y), packh2(v.z, v.w));
    }
}

// 128x128x128 fp16 GEMM, 16 warps. Warp w: rg=w>>2 rows [32rg,+32), cg=w&3
// cols [32cg,+32). 8 k-steps of 16. acc[(mi*4+nt)*4 + 2*h + e] (fp32).
// A frag (m16k16): a0=(lq, 2lm..+1), a1=(lq+8, same), a2=(lq, 2lm+8..), a3=(lq+8,..)
// B frag (k16n8):  b0=(k=2lm..+1, n=lq), b1=(k=2lm+8..+9, n=lq)
DEVINL void gemm16(uint32_t sbA, uint32_t sbW, int rg, int cg, int lq, int lm,
                   float acc[32]) {
    const uint32_t bA = sbA + (uint32_t)(32 * rg + lq) * RS16 + 4u * lm;
    const uint32_t bB = sbW + (uint32_t)(32 * cg + lq) * RS16 + 4u * lm;
#pragma unroll
    for (int kk = 0; kk < 8; kk++) {
        uint32_t a[2][4];
#pragma unroll
        for (int mi = 0; mi < 2; mi++) {
            const uint32_t r = bA + (uint32_t)(mi * 16 * RS16 + kk * 32);
            a[mi][0] = lds32(r);
            a[mi][1] = lds32(r + 8 * RS16);
            a[mi][2] = lds32(r + 16);
            a[mi][3] = lds32(r + 8 * RS16 + 16);
        }
#pragma unroll
        for (int nt = 0; nt < 4; nt++) {
            const uint32_t rb = bB + (uint32_t)(nt * 8 * RS16 + kk * 32);
            uint32_t b0 = lds32(rb);
            uint32_t b1 = lds32(rb + 16);
            mma16(acc + nt * 4,      a[0], b0, b1);
            mma16(acc + 16 + nt * 4, a[1], b0, b1);
        }
    }
}

// Extract thread's 8 contiguous logical cols (j = 2*nt+e) for row-rep (mi,h).
#define ACCJ(mi, h, j) acc[((mi) * 4 + ((j) >> 1)) * 4 + 2 * (h) + ((j) & 1)]

// ---------------- node projection kernel ----------------
// SMEM: Ws16[0,34816) Wd16[34816,69632) A16[69632,104448) b1[104448,+512)
#define NODE_SMEM 104960

__global__ void __launch_bounds__(512, 1)
node_kernel(const float* __restrict__ nfeat, const float* __restrict__ Ws,
            const float* __restrict__ Wd, const float* __restrict__ b1,
            float* __restrict__ nfeat_out) {
    extern __shared__ char smem[];
    const uint32_t sb = smem_u32(smem);
    const uint32_t sWS = sb, sWD = sb + T16_BYTES, sA = sb + 2 * T16_BYTES;
    const uint32_t sB1 = sb + 3 * T16_BYTES;
    const int tid = threadIdx.x, w = tid >> 5, lane = tid & 31;
    const int lq = lane >> 2, lm = lane & 3, rg = w >> 2, cg = w & 3;

    load_weight16(sWS, Ws, tid);
    load_weight16(sWD, Wd, tid);
    if (tid < 128) ((float*)(smem + 3 * T16_BYTES))[tid] = __ldg(b1 + tid);

    const int base = blockIdx.x * 128;
#pragma unroll
    for (int i = 0; i < 8; i++) {
        const int f4 = tid + 512 * i;
        const int row = f4 >> 5, c4 = f4 & 31;
        const int ng = base + row;
        const bool v = ng < N_NODES;
        float4 x = v ? __ldg((const float4*)(nfeat + (size_t)ng * 128) + c4)
                     : make_float4(0.f, 0.f, 0.f, 0.f);
        if (v) *((float4*)(nfeat_out + (size_t)ng * 128) + c4) = x;  // passthrough
        sts64(adr16(sA, row, c4 * 8), packh2(x.x, x.y), packh2(x.z, x.w));
    }
    __syncthreads();

    const int Lb = 32 * cg + 8 * lm;                 // thread's logical col base
    const float4 bb0 = lds128f(sB1 + (uint32_t)Lb * 4);
    const float4 bb1 = lds128f(sB1 + (uint32_t)Lb * 4 + 16);

    float acc[32];
#pragma unroll
    for (int i = 0; i < 32; i++) acc[i] = 0.f;
    gemm16(sA, sWS, rg, cg, lq, lm, acc);
#pragma unroll
    for (int mi = 0; mi < 2; mi++)
#pragma unroll
    for (int h = 0; h < 2; h++) {
        const int ng = base + 32 * rg + 16 * mi + 8 * h + lq;
        if (ng < N_NODES) {
            float4 o0, o1;
            o0.x = ACCJ(mi, h, 0) + bb0.x;  o0.y = ACCJ(mi, h, 1) + bb0.y;
            o0.z = ACCJ(mi, h, 2) + bb0.z;  o0.w = ACCJ(mi, h, 3) + bb0.w;
            o1.x = ACCJ(mi, h, 4) + bb1.x;  o1.y = ACCJ(mi, h, 5) + bb1.y;
            o1.z = ACCJ(mi, h, 6) + bb1.z;  o1.w = ACCJ(mi, h, 7) + bb1.w;
            float4* p = (float4*)(g_srcproj + (size_t)ng * 128 + Lb);
            p[0] = o0; p[1] = o1;
        }
    }

#pragma unroll
    for (int i = 0; i < 32; i++) acc[i] = 0.f;
    gemm16(sA, sWD, rg, cg, lq, lm, acc);
#pragma unroll
    for (int mi = 0; mi < 2; mi++)
#pragma unroll
    for (int h = 0; h < 2; h++) {
        const int ng = base + 32 * rg + 16 * mi + 8 * h + lq;
        if (ng < N_NODES) {
            float4 o0, o1;
            o0.x = ACCJ(mi, h, 0);  o0.y = ACCJ(mi, h, 1);
            o0.z = ACCJ(mi, h, 2);  o0.w = ACCJ(mi, h, 3);
            o1.x = ACCJ(mi, h, 4);  o1.y = ACCJ(mi, h, 5);
            o1.z = ACCJ(mi, h, 6);  o1.w = ACCJ(mi, h, 7);
            float4* p = (float4*)(g_dstproj + (size_t)ng * 128 + Lb);
            p[0] = o0; p[1] = o1;
        }
    }
}

// ---------------- fused edge kernel (persistent, 512 thr) ----------------
// SMEM: We16[0,34816) Wo16[34816,69632) A16[69632,104448) STG[104448,169984)
//       LN[169984,+4096) bo@174080 gamma@174592 beta@175104 mbar@175616(+128)
#define EDGE_SMEM 175744

// Group-local prefetch of NEXT tile's efeat (raw fp32) into the staging buffer.
// Each thread's cp.asyncs cover exactly the bytes IT will convert at the next
// tile start (identical f4 mapping), so cp.async.wait_group alone orders them.
DEVINL void prefetch_efeat_grp(uint32_t sSTG, const float* __restrict__ efeat,
                               int tile, int rg, int gt) {
    const int base = tile * 128 + 32 * rg;
#pragma unroll
    for (int i = 0; i < 8; i++) {
        const int f4 = gt + 128 * i;                 // 0..1023 within group
        const int row = f4 >> 5, c4 = f4 & 31;       // local row 0..31, col4 0..31
        const int e = base + row;
        const bool v = e < N_EDGES;
        const float* g = efeat + (size_t)(v ? e : 0) * 128 + c4 * 4;
        cpasync16(sSTG + (uint32_t)(32 * rg + row) * RSTG + (uint32_t)c4 * 16u,
                  g, v ? 16 : 0);
    }
    cpcommit();
}

// Convert this thread's own staged fp32 bytes -> fp16 A tile.
DEVINL void convert_rows(uint32_t sA16, uint32_t sSTG, int rg, int gt) {
#pragma unroll
    for (int i = 0; i < 8; i++) {
        const int f4 = gt + 128 * i;
        const int row = 32 * rg + (f4 >> 5), c4 = f4 & 31;
        float4 v = lds128f(sSTG + (uint32_t)row * RSTG + (uint32_t)c4 * 16u);
        sts64(adr16(sA16, row, c4 * 8), packh2(v.x, v.y), packh2(v.z, v.w));
    }
}

__global__ void __launch_bounds__(512, 1)
edge_kernel(const float* __restrict__ efeat, const int* __restrict__ src,
            const int* __restrict__ dst, const float* __restrict__ We,
            const float* __restrict__ Wo, const float* __restrict__ bo,
            const float* __restrict__ gamma, const float* __restrict__ beta,
            float* __restrict__ out) {
    extern __shared__ char smem[];
    const uint32_t sb = smem_u32(smem);
    const uint32_t sWE = sb, sWO = sb + T16_BYTES, sA16 = sb + 2 * T16_BYTES;
    const uint32_t sSTG = sb + 3 * T16_BYTES;
    const uint32_t sLN = sSTG + STG_BYTES;
    const uint32_t sBO = sLN + 4096, sGA = sBO + 512, sBE = sGA + 512;
    const uint32_t sMB = sBE + 512;                  // 16 mbarriers (4 grp x 4 pts)
    const int tid = threadIdx.x, w = tid >> 5, lane = tid & 31;
    const int lq = lane >> 2, lm = lane & 3, rg = w >> 2, cg = w & 3;
    const int gt = tid & 127;                        // thread id within rg-group
    const uint32_t mb0 = sMB + (uint32_t)rg * 32u;   // this group's 4 barriers

    load_weight16(sWE, We, tid);
    load_weight16(sWO, Wo, tid);
    if (tid < 128) {
        ((float*)(smem + (sBO - sb)))[tid] = __ldg(bo + tid);
        ((float*)(smem + (sGA - sb)))[tid] = __ldg(gamma + tid);
        ((float*)(smem + (sBE - sb)))[tid] = __ldg(beta + tid);
    }
    if (tid < 16) mbar_init(sMB + (uint32_t)tid * 8u, 128);
    // prologue: prefetch first tile's efeat (raw fp32) into staging
    prefetch_efeat_grp(sSTG, efeat, blockIdx.x, rg, gt);
    __syncthreads();      // weights/biases/mbarriers visible; groups decouple after

    const int Lb = 32 * cg + 8 * lm;                 // thread's logical col base
    const float4 bo0 = lds128f(sBO + (uint32_t)Lb * 4);
    const float4 bo1 = lds128f(sBO + (uint32_t)Lb * 4 + 16);
    const float4 ga0 = lds128f(sGA + (uint32_t)Lb * 4);
    const float4 ga1 = lds128f(sGA + (uint32_t)Lb * 4 + 16);
    const float4 be0 = lds128f(sBE + (uint32_t)Lb * 4);
    const float4 be1 = lds128f(sBE + (uint32_t)Lb * 4 + 16);

    uint32_t ph = 0;                                 // shared parity, 4 pts/tile

    for (int tile = blockIdx.x; tile < ETILES; tile += GRID_E) {
        const int base = tile * 128;
        cpwait0();
        // fp32 staging -> fp16 A tile (own bytes only; A16 rows free since
        // the group's gsync(e) of the previous tile followed its GEMM2).
        convert_rows(sA16, sSTG, rg, gt);
        gsync(mb0 + 0, ph);                   // (a) group's 32 A16 rows ready

        // prefetch gather indices early (consumed after GEMM1)
        int si[4], di[4];
        bool vr[4];
#pragma unroll
        for (int mi = 0; mi < 2; mi++)
#pragma unroll
        for (int h = 0; h < 2; h++) {
            const int e = base + 32 * rg + 16 * mi + 8 * h + lq;
            const bool v = e < N_EDGES;
            vr[mi * 2 + h] = v;
            si[mi * 2 + h] = v ? __ldg(src + e) : 0;
            di[mi * 2 + h] = v ? __ldg(dst + e) : 0;
        }

        float acc[32];
#pragma unroll
        for (int i = 0; i < 32; i++) acc[i] = 0.f;
        gemm16(sA16, sWE, rg, cg, lq, lm, acc);   // h-pre = efeat @ We^T
        gsync(mb0 + 8, ph);                   // (c) group done reading its A rows

        // epilogue1: + srcproj[src] (b1 folded) + dstproj[dst], SiLU, act -> A16
#pragma unroll
        for (int mi = 0; mi < 2; mi++)
#pragma unroll
        for (int h = 0; h < 2; h++) {
            const int R = 32 * rg + 16 * mi + 8 * h + lq;
            const float4* ps = (const float4*)(g_srcproj + (size_t)si[mi * 2 + h] * 128 + Lb);
            const float4* pd = (const float4*)(g_dstproj + (size_t)di[mi * 2 + h] * 128 + Lb);
            float4 s0 = __ldg(ps), s1 = __ldg(ps + 1);
            float4 d0 = __ldg(pd), d1 = __ldg(pd + 1);
            float x0 = silu_f(ACCJ(mi, h, 0) + s0.x + d0.x);
            float x1 = silu_f(ACCJ(mi, h, 1) + s0.y + d0.y);
            float x2 = silu_f(ACCJ(mi, h, 2) + s0.z + d0.z);
            float x3 = silu_f(ACCJ(mi, h, 3) + s0.w + d0.w);
            float x4 = silu_f(ACCJ(mi, h, 4) + s1.x + d1.x);
            float x5 = silu_f(ACCJ(mi, h, 5) + s1.y + d1.y);
            float x6 = silu_f(ACCJ(mi, h, 6) + s1.z + d1.z);
            float x7 = silu_f(ACCJ(mi, h, 7) + s1.w + d1.w);
            sts128(adr16(sA16, R, Lb * 2),
                   packh2(x0, x1), packh2(x2, x3), packh2(x4, x5), packh2(x6, x7));
        }
        gsync(mb0 + 16, ph);                  // (d) group's act rows complete

#pragma unroll
        for (int i = 0; i < 32; i++) acc[i] = 0.f;
        gemm16(sA16, sWO, rg, cg, lq, lm, acc);   // o-pre = act @ Wo^T

        // epilogue2a: + bo, LayerNorm partials (quad shfl + cross-warp SMEM)
#pragma unroll
        for (int mi = 0; mi < 2; mi++)
#pragma unroll
        for (int h = 0; h < 2; h++) {
            float s = 0.f, q = 0.f;
#pragma unroll
            for (int j = 0; j < 8; j++) {
                const float b = (j < 4) ? ((const float*)&bo0)[j] : ((const float*)&bo1)[j - 4];
                float x = ACCJ(mi, h, j) + b;
                ACCJ(mi, h, j) = x;
                s += x;
                q += x * x;
            }
            s += __shfl_xor_sync(0xffffffffu, s, 1);
            q += __shfl_xor_sync(0xffffffffu, q, 1);
            s += __shfl_xor_sync(0xffffffffu, s, 2);
            q += __shfl_xor_sync(0xffffffffu, q, 2);
            if (lm == 0) {
                const int R = 32 * rg + 16 * mi + 8 * h + lq;
                sts64f(sLN + (uint32_t)(cg * 128 + R) * 8, s, q);
            }
        }
        gsync(mb0 + 24, ph);                  // (e) LN partials visible

        // prefetch next tile's efeat into staging (overlaps epilogue2b)
        if (tile + GRID_E < ETILES)
            prefetch_efeat_grp(sSTG, efeat, tile + GRID_E, rg, gt);

        // epilogue2b: normalize, affine, + residual efeat (L2-hot), store
#pragma unroll
        for (int mi = 0; mi < 2; mi++)
#pragma unroll
        for (int h = 0; h < 2; h++) {
            const int R = 32 * rg + 16 * mi + 8 * h + lq;
            const int e = base + R;
            const bool v = vr[mi * 2 + h];
            float2 p0 = *(float2*)(smem + (sLN - sb) + (uint32_t)R * 8);
            float2 p1 = *(float2*)(smem + (sLN - sb) + (uint32_t)(128 + R) * 8);
            float2 p2 = *(float2*)(smem + (sLN - sb) + (uint32_t)(256 + R) * 8);
            float2 p3 = *(float2*)(smem + (sLN - sb) + (uint32_t)(384 + R) * 8);
            const float mu  = (p0.x + p1.x + p2.x + p3.x) * 0.0078125f;
            const float var = (p0.y + p1.y + p2.y + p3.y) * 0.0078125f - mu * mu;
            const float rs  = rsqrtf(var + 1e-5f);
            const float4* pe = (const float4*)(efeat + (size_t)(v ? e : 0) * 128 + Lb);
            float4 r0 = v ? __ldg(pe)     : make_float4(0.f, 0.f, 0.f, 0.f);
            float4 r1 = v ? __ldg(pe + 1) : make_float4(0.f, 0.f, 0.f, 0.f);
            float4 o0, o1;
            o0.x = (ACCJ(mi, h, 0) - mu) * rs * ga0.x + be0.x + r0.x;
            o0.y = (ACCJ(mi, h, 1) - mu) * rs * ga0.y + be0.y + r0.y;
            o0.z = (ACCJ(mi, h, 2) - mu) * rs * ga0.z + be0.z + r0.z;
            o0.w = (ACCJ(mi, h, 3) - mu) * rs * ga0.w + be0.w + r0.w;
            o1.x = (ACCJ(mi, h, 4) - mu) * rs * ga1.x + be1.x + r1.x;
            o1.y = (ACCJ(mi, h, 5) - mu) * rs * ga1.y + be1.y + r1.y;
            o1.z = (ACCJ(mi, h, 6) - mu) * rs * ga1.z + be1.z + r1.z;
            o1.w = (ACCJ(mi, h, 7) - mu) * rs * ga1.w + be1.w + r1.w;
            if (v) {
                float4* po = (float4*)(out + (size_t)e * 128 + Lb);
                po[0] = o0; po[1] = o1;
            }
        }
        ph ^= 1;                              // all 4 barriers used once per tile
    }
}

// ---------------- launch ----------------

extern "C" void kernel_launch(void* const* d_in, const int* in_sizes, int n_in,
                              void* d_out, int out_size) {
    const float* efeat = (const float*)d_in[0];
    const float* nfeat = (const float*)d_in[1];
    const int*   src   = (const int*)d_in[2];
    const int*   dst   = (const int*)d_in[3];
    const float* We    = (const float*)d_in[4];
    const float* Ws    = (const float*)d_in[5];
    const float* Wd    = (const float*)d_in[6];
    const float* b1    = (const float*)d_in[7];
    const float* Wo    = (const float*)d_in[8];
    const float* bo    = (const float*)d_in[9];
    const float* gamma = (const float*)d_in[10];
    const float* beta  = (const float*)d_in[11];
    float* out = (float*)d_out;

    cudaFuncSetAttribute(node_kernel, cudaFuncAttributeMaxDynamicSharedMemorySize, NODE_SMEM);
    cudaFuncSetAttribute(edge_kernel, cudaFuncAttributeMaxDynamicSharedMemorySize, EDGE_SMEM);

    // node kernel also writes the nfeat passthrough output
    node_kernel<<<NTILES, 512, NODE_SMEM>>>(nfeat, Ws, Wd, b1,
                                            out + (size_t)N_EDGES * 128);
    edge_kernel<<<GRID_E, 512, EDGE_SMEM>>>(efeat, src, dst, We, Wo, bo, gamma, beta, out);
}

// round 13
// speedup vs baseline: 1.9360x; 1.1709x over previous
#include <cuda_runtime.h>
#include <cuda_fp16.h>
#include <cstdint>

#define DEVINL static __device__ __forceinline__

#define N_EDGES 600000
#define N_NODES 50000
#define ETILES 4688     // ceil(600000/128)
#define NTILES 391      // ceil(50000/128)
#define GRID_E 148

// fp16 tile geometry: 128 rows x 128 cols, row stride 272B (136 halfs).
// 272/4 = 68 ≡ 4 (mod 32) => conflict-free for the mma fragment pattern with
// addresses LINEAR in k/mi/nt (LDS immediates).
#define RS16 272
#define T16_BYTES (128 * RS16)      // 34816
// fp32 staging tile for cp.async efeat prefetch (plain 512B rows).
#define RSTG 512
#define STG_BYTES (128 * RSTG)      // 65536

// Node projection scratch in FP16 (b1 folded into srcproj): 2 x 12.8MB ->
// both tables fully L2-resident (126MB L2), and gathers are one LDG.128/row.
static __device__ uint16_t g_srcproj[(size_t)N_NODES * 128];
static __device__ uint16_t g_dstproj[(size_t)N_NODES * 128];

// ---------------- helpers ----------------

DEVINL uint32_t smem_u32(const void* p) {
    uint32_t a;
    asm("{ .reg .u64 t; cvta.to.shared.u64 t, %1; cvt.u32.u64 %0, t; }" : "=r"(a) : "l"(p));
    return a;
}
// pack two f32 -> f16x2 {lo, hi} (first PTX src = high half)
DEVINL uint32_t packh2(float lo, float hi) {
    uint32_t r;
    asm("cvt.rn.f16x2.f32 %0, %1, %2;" : "=r"(r) : "f"(hi), "f"(lo));
    return r;
}
DEVINL float2 h2f2(uint32_t h) {
    return __half22float2(*reinterpret_cast<const __half2*>(&h));
}
DEVINL uint32_t lds32(uint32_t a) {
    uint32_t v;
    asm volatile("ld.shared.b32 %0, [%1];" : "=r"(v) : "r"(a));
    return v;
}
DEVINL float4 lds128f(uint32_t a) {
    float4 v;
    asm volatile("ld.shared.v4.f32 {%0,%1,%2,%3}, [%4];"
                 : "=f"(v.x), "=f"(v.y), "=f"(v.z), "=f"(v.w) : "r"(a));
    return v;
}
DEVINL void sts64f(uint32_t a, float x, float y) {
    asm volatile("st.shared.v2.f32 [%0], {%1,%2};" :: "r"(a), "f"(x), "f"(y));
}
DEVINL void sts64(uint32_t a, uint32_t x, uint32_t y) {
    asm volatile("st.shared.v2.b32 [%0], {%1,%2};" :: "r"(a), "r"(x), "r"(y));
}
DEVINL void sts128(uint32_t a, uint32_t x, uint32_t y, uint32_t z, uint32_t w) {
    asm volatile("st.shared.v4.b32 [%0], {%1,%2,%3,%4};" :: "r"(a), "r"(x), "r"(y), "r"(z), "r"(w));
}
DEVINL void cpasync16(uint32_t s, const void* g, int srcbytes) {
    asm volatile("cp.async.cg.shared.global [%0], [%1], 16, %2;"
                 :: "r"(s), "l"(g), "r"(srcbytes));
}
DEVINL void cpcommit() { asm volatile("cp.async.commit_group;" ::: "memory"); }
DEVINL void cpwait0()  { asm volatile("cp.async.wait_group 0;" ::: "memory"); }

// mbarrier-based group sync (R11 win; avoids BAR hw, which faulted in R9/R10).
DEVINL void mbar_init(uint32_t a, uint32_t cnt) {
    asm volatile("mbarrier.init.shared.b64 [%0], %1;" :: "r"(a), "r"(cnt) : "memory");
}
DEVINL void gsync(uint32_t mb, uint32_t ph) {
    asm volatile(
        "{\n\t.reg .pred P;\n\t"
        "mbarrier.arrive.shared.b64 _, [%0];\n\t"
        "LW%=:\n\t"
        "mbarrier.try_wait.parity.acquire.cta.shared::cta.b64 P, [%0], %1, 0x989680;\n\t"
        "@P bra.uni LD%=;\n\t"
        "bra.uni LW%=;\n\t"
        "LD%=:\n\t}"
        :: "r"(mb), "r"(ph) : "memory");
}

// silu(x) = x*sigmoid(x) = h + h*tanh(h), h = x/2  (1 MUFU)
DEVINL float silu_f(float x) {
    float h = 0.5f * x, t;
    asm("tanh.approx.f32 %0, %1;" : "=f"(t) : "f"(h));
    return fmaf(h, t, h);
}

// Out-dim permutation: n = 32c+8a+2b+e -> 32c+8b+2a+e  (swap 2-bit fields).
// Thread's D-fragment columns become CONTIGUOUS logical cols 32*cg+8*lm+{0..7}.
DEVINL int permn(int n) {
    return (n & 0x61) | ((n & 6) << 2) | ((n >> 2) & 6);
}

// fp16 tile address: row r, BYTE column cb.
DEVINL uint32_t adr16(uint32_t b, int r, int cb) {
    return b + (uint32_t)r * (uint32_t)RS16 + (uint32_t)cb;
}

// m16n8k16 fp16 HMMA, fp32 accum (base-target PTX, sm_80+)
DEVINL void mma16(float* d, const uint32_t* a, uint32_t b0, uint32_t b1) {
    asm volatile(
        "mma.sync.aligned.m16n8k16.row.col.f32.f16.f16.f32 "
        "{%0,%1,%2,%3}, {%4,%5,%6,%7}, {%8,%9}, {%0,%1,%2,%3};"
        : "+f"(d[0]), "+f"(d[1]), "+f"(d[2]), "+f"(d[3])
        : "r"(a[0]), "r"(a[1]), "r"(a[2]), "r"(a[3]), "r"(b0), "r"(b1));
}

// Load [128 out][128 in] row-major fp32 weight into fp16 SMEM (out-rows permuted).
DEVINL void load_weight16(uint32_t sbW, const float* __restrict__ W, int tid) {
#pragma unroll 1
    for (int i = tid; i < 4096; i += 512) {
        int n = i >> 5, k4 = (i & 31) << 2;      // k4 = starting k index
        float4 v = __ldg((const float4*)W + i);
        sts64(adr16(sbW, permn(n), k4 * 2), packh2(v.x, v.y), packh2(v.z, v.w));
    }
}

// 128x128x128 fp16 GEMM, 16 warps. Warp w: rg=w>>2 rows [32rg,+32), cg=w&3
// cols [32cg,+32). 8 k-steps of 16. acc[(mi*4+nt)*4 + 2*h + e] (fp32).
DEVINL void gemm16(uint32_t sbA, uint32_t sbW, int rg, int cg, int lq, int lm,
                   float acc[32]) {
    const uint32_t bA = sbA + (uint32_t)(32 * rg + lq) * RS16 + 4u * lm;
    const uint32_t bB = sbW + (uint32_t)(32 * cg + lq) * RS16 + 4u * lm;
#pragma unroll
    for (int kk = 0; kk < 8; kk++) {
        uint32_t a[2][4];
#pragma unroll
        for (int mi = 0; mi < 2; mi++) {
            const uint32_t r = bA + (uint32_t)(mi * 16 * RS16 + kk * 32);
            a[mi][0] = lds32(r);
            a[mi][1] = lds32(r + 8 * RS16);
            a[mi][2] = lds32(r + 16);
            a[mi][3] = lds32(r + 8 * RS16 + 16);
        }
#pragma unroll
        for (int nt = 0; nt < 4; nt++) {
            const uint32_t rb = bB + (uint32_t)(nt * 8 * RS16 + kk * 32);
            uint32_t b0 = lds32(rb);
            uint32_t b1 = lds32(rb + 16);
            mma16(acc + nt * 4,      a[0], b0, b1);
            mma16(acc + 16 + nt * 4, a[1], b0, b1);
        }
    }
}

// Extract thread's 8 contiguous logical cols (j = 2*nt+e) for row-rep (mi,h).
#define ACCJ(mi, h, j) acc[((mi) * 4 + ((j) >> 1)) * 4 + 2 * (h) + ((j) & 1)]

// ---------------- node projection kernel ----------------
// SMEM: Ws16[0,34816) Wd16[34816,69632) A16[69632,104448) b1[104448,+512)
#define NODE_SMEM 104960

__global__ void __launch_bounds__(512, 1)
node_kernel(const float* __restrict__ nfeat, const float* __restrict__ Ws,
            const float* __restrict__ Wd, const float* __restrict__ b1,
            float* __restrict__ nfeat_out) {
    extern __shared__ char smem[];
    const uint32_t sb = smem_u32(smem);
    const uint32_t sWS = sb, sWD = sb + T16_BYTES, sA = sb + 2 * T16_BYTES;
    const uint32_t sB1 = sb + 3 * T16_BYTES;
    const int tid = threadIdx.x, w = tid >> 5, lane = tid & 31;
    const int lq = lane >> 2, lm = lane & 3, rg = w >> 2, cg = w & 3;

    load_weight16(sWS, Ws, tid);
    load_weight16(sWD, Wd, tid);
    if (tid < 128) ((float*)(smem + 3 * T16_BYTES))[tid] = __ldg(b1 + tid);

    const int base = blockIdx.x * 128;
#pragma unroll
    for (int i = 0; i < 8; i++) {
        const int f4 = tid + 512 * i;
        const int row = f4 >> 5, c4 = f4 & 31;
        const int ng = base + row;
        const bool v = ng < N_NODES;
        float4 x = v ? __ldg((const float4*)(nfeat + (size_t)ng * 128) + c4)
                     : make_float4(0.f, 0.f, 0.f, 0.f);
        if (v) *((float4*)(nfeat_out + (size_t)ng * 128) + c4) = x;  // passthrough
        sts64(adr16(sA, row, c4 * 8), packh2(x.x, x.y), packh2(x.z, x.w));
    }
    __syncthreads();

    const int Lb = 32 * cg + 8 * lm;                 // thread's logical col base
    const float4 bb0 = lds128f(sB1 + (uint32_t)Lb * 4);
    const float4 bb1 = lds128f(sB1 + (uint32_t)Lb * 4 + 16);

    float acc[32];
#pragma unroll
    for (int i = 0; i < 32; i++) acc[i] = 0.f;
    gemm16(sA, sWS, rg, cg, lq, lm, acc);
#pragma unroll
    for (int mi = 0; mi < 2; mi++)
#pragma unroll
    for (int h = 0; h < 2; h++) {
        const int ng = base + 32 * rg + 16 * mi + 8 * h + lq;
        if (ng < N_NODES) {
            uint4 o;
            o.x = packh2(ACCJ(mi, h, 0) + bb0.x, ACCJ(mi, h, 1) + bb0.y);
            o.y = packh2(ACCJ(mi, h, 2) + bb0.z, ACCJ(mi, h, 3) + bb0.w);
            o.z = packh2(ACCJ(mi, h, 4) + bb1.x, ACCJ(mi, h, 5) + bb1.y);
            o.w = packh2(ACCJ(mi, h, 6) + bb1.z, ACCJ(mi, h, 7) + bb1.w);
            *(uint4*)(g_srcproj + (size_t)ng * 128 + Lb) = o;
        }
    }

#pragma unroll
    for (int i = 0; i < 32; i++) acc[i] = 0.f;
    gemm16(sA, sWD, rg, cg, lq, lm, acc);
#pragma unroll
    for (int mi = 0; mi < 2; mi++)
#pragma unroll
    for (int h = 0; h < 2; h++) {
        const int ng = base + 32 * rg + 16 * mi + 8 * h + lq;
        if (ng < N_NODES) {
            uint4 o;
            o.x = packh2(ACCJ(mi, h, 0), ACCJ(mi, h, 1));
            o.y = packh2(ACCJ(mi, h, 2), ACCJ(mi, h, 3));
            o.z = packh2(ACCJ(mi, h, 4), ACCJ(mi, h, 5));
            o.w = packh2(ACCJ(mi, h, 6), ACCJ(mi, h, 7));
            *(uint4*)(g_dstproj + (size_t)ng * 128 + Lb) = o;
        }
    }
}

// ---------------- fused edge kernel (persistent, 512 thr) ----------------
// SMEM: We16[0,34816) Wo16[34816,69632) A16[69632,104448) STG[104448,169984)
//       LN[169984,+4096) bo@174080 gamma@174592 beta@175104 mbar@175616(+128)
#define EDGE_SMEM 175744

// Group-local prefetch of NEXT tile's efeat (raw fp32) into the staging buffer.
DEVINL void prefetch_efeat_grp(uint32_t sSTG, const float* __restrict__ efeat,
                               int tile, int rg, int gt) {
    const int base = tile * 128 + 32 * rg;
#pragma unroll
    for (int i = 0; i < 8; i++) {
        const int f4 = gt + 128 * i;                 // 0..1023 within group
        const int row = f4 >> 5, c4 = f4 & 31;       // local row 0..31, col4 0..31
        const int e = base + row;
        const bool v = e < N_EDGES;
        const float* g = efeat + (size_t)(v ? e : 0) * 128 + c4 * 4;
        cpasync16(sSTG + (uint32_t)(32 * rg + row) * RSTG + (uint32_t)c4 * 16u,
                  g, v ? 16 : 0);
    }
    cpcommit();
}

// Convert this thread's own staged fp32 bytes -> fp16 A tile.
DEVINL void convert_rows(uint32_t sA16, uint32_t sSTG, int rg, int gt) {
#pragma unroll
    for (int i = 0; i < 8; i++) {
        const int f4 = gt + 128 * i;
        const int row = 32 * rg + (f4 >> 5), c4 = f4 & 31;
        float4 v = lds128f(sSTG + (uint32_t)row * RSTG + (uint32_t)c4 * 16u);
        sts64(adr16(sA16, row, c4 * 8), packh2(v.x, v.y), packh2(v.z, v.w));
    }
}

__global__ void __launch_bounds__(512, 1)
edge_kernel(const float* __restrict__ efeat, const int* __restrict__ src,
            const int* __restrict__ dst, const float* __restrict__ We,
            const float* __restrict__ Wo, const float* __restrict__ bo,
            const float* __restrict__ gamma, const float* __restrict__ beta,
            float* __restrict__ out) {
    extern __shared__ char smem[];
    const uint32_t sb = smem_u32(smem);
    const uint32_t sWE = sb, sWO = sb + T16_BYTES, sA16 = sb + 2 * T16_BYTES;
    const uint32_t sSTG = sb + 3 * T16_BYTES;
    const uint32_t sLN = sSTG + STG_BYTES;
    const uint32_t sBO = sLN + 4096, sGA = sBO + 512, sBE = sGA + 512;
    const uint32_t sMB = sBE + 512;                  // 16 mbarriers (4 grp x 4 pts)
    const int tid = threadIdx.x, w = tid >> 5, lane = tid & 31;
    const int lq = lane >> 2, lm = lane & 3, rg = w >> 2, cg = w & 3;
    const int gt = tid & 127;                        // thread id within rg-group
    const uint32_t mb0 = sMB + (uint32_t)rg * 32u;   // this group's 4 barriers

    load_weight16(sWE, We, tid);
    load_weight16(sWO, Wo, tid);
    if (tid < 128) {
        ((float*)(smem + (sBO - sb)))[tid] = __ldg(bo + tid);
        ((float*)(smem + (sGA - sb)))[tid] = __ldg(gamma + tid);
        ((float*)(smem + (sBE - sb)))[tid] = __ldg(beta + tid);
    }
    if (tid < 16) mbar_init(sMB + (uint32_t)tid * 8u, 128);
    // prologue: prefetch first tile's efeat (raw fp32) into staging
    prefetch_efeat_grp(sSTG, efeat, blockIdx.x, rg, gt);
    __syncthreads();      // weights/biases/mbarriers visible; groups decouple after

    const int Lb = 32 * cg + 8 * lm;                 // thread's logical col base
    const float4 bo0 = lds128f(sBO + (uint32_t)Lb * 4);
    const float4 bo1 = lds128f(sBO + (uint32_t)Lb * 4 + 16);
    const float4 ga0 = lds128f(sGA + (uint32_t)Lb * 4);
    const float4 ga1 = lds128f(sGA + (uint32_t)Lb * 4 + 16);
    const float4 be0 = lds128f(sBE + (uint32_t)Lb * 4);
    const float4 be1 = lds128f(sBE + (uint32_t)Lb * 4 + 16);

    uint32_t ph = 0;                                 // shared parity, 4 pts/tile

    for (int tile = blockIdx.x; tile < ETILES; tile += GRID_E) {
        const int base = tile * 128;
        cpwait0();
        convert_rows(sA16, sSTG, rg, gt);     // staged fp32 -> fp16 A tile
        gsync(mb0 + 0, ph);                   // (a) group's 32 A16 rows ready

        // Load indices AND issue all gather loads now (fp16 tables: the whole
        // gather is 8 x uint4 = 32 regs) so their L2 latency hides under GEMM1.
        bool vr[4];
        uint4 sg[4], dg[4];
#pragma unroll
        for (int mi = 0; mi < 2; mi++)
#pragma unroll
        for (int h = 0; h < 2; h++) {
            const int e = base + 32 * rg + 16 * mi + 8 * h + lq;
            const bool v = e < N_EDGES;
            vr[mi * 2 + h] = v;
            const int si = v ? __ldg(src + e) : 0;
            const int di = v ? __ldg(dst + e) : 0;
            sg[mi * 2 + h] = __ldg((const uint4*)(g_srcproj + (size_t)si * 128 + Lb));
            dg[mi * 2 + h] = __ldg((const uint4*)(g_dstproj + (size_t)di * 128 + Lb));
        }

        float acc[32];
#pragma unroll
        for (int i = 0; i < 32; i++) acc[i] = 0.f;
        gemm16(sA16, sWE, rg, cg, lq, lm, acc);   // h-pre = efeat @ We^T
        gsync(mb0 + 8, ph);                   // (c) group done reading its A rows

        // epilogue1: + srcproj[src] (b1 folded) + dstproj[dst], SiLU, act -> A16
#pragma unroll
        for (int mi = 0; mi < 2; mi++)
#pragma unroll
        for (int h = 0; h < 2; h++) {
            const int R = 32 * rg + 16 * mi + 8 * h + lq;
            const uint4 sv = sg[mi * 2 + h], dv = dg[mi * 2 + h];
            float2 s0 = h2f2(sv.x), s1 = h2f2(sv.y), s2 = h2f2(sv.z), s3 = h2f2(sv.w);
            float2 d0 = h2f2(dv.x), d1 = h2f2(dv.y), d2 = h2f2(dv.z), d3 = h2f2(dv.w);
            float x0 = silu_f(ACCJ(mi, h, 0) + s0.x + d0.x);
            float x1 = silu_f(ACCJ(mi, h, 1) + s0.y + d0.y);
            float x2 = silu_f(ACCJ(mi, h, 2) + s1.x + d1.x);
            float x3 = silu_f(ACCJ(mi, h, 3) + s1.y + d1.y);
            float x4 = silu_f(ACCJ(mi, h, 4) + s2.x + d2.x);
            float x5 = silu_f(ACCJ(mi, h, 5) + s2.y + d2.y);
            float x6 = silu_f(ACCJ(mi, h, 6) + s3.x + d3.x);
            float x7 = silu_f(ACCJ(mi, h, 7) + s3.y + d3.y);
            sts128(adr16(sA16, R, Lb * 2),
                   packh2(x0, x1), packh2(x2, x3), packh2(x4, x5), packh2(x6, x7));
        }
        gsync(mb0 + 16, ph);                  // (d) group's act rows complete

#pragma unroll
        for (int i = 0; i < 32; i++) acc[i] = 0.f;
        gemm16(sA16, sWO, rg, cg, lq, lm, acc);   // o-pre = act @ Wo^T

        // epilogue2a: + bo, LayerNorm partials (quad shfl + cross-warp SMEM)
#pragma unroll
        for (int mi = 0; mi < 2; mi++)
#pragma unroll
        for (int h = 0; h < 2; h++) {
            float s = 0.f, q = 0.f;
#pragma unroll
            for (int j = 0; j < 8; j++) {
                const float b = (j < 4) ? ((const float*)&bo0)[j] : ((const float*)&bo1)[j - 4];
                float x = ACCJ(mi, h, j) + b;
                ACCJ(mi, h, j) = x;
                s += x;
                q += x * x;
            }
            s += __shfl_xor_sync(0xffffffffu, s, 1);
            q += __shfl_xor_sync(0xffffffffu, q, 1);
            s += __shfl_xor_sync(0xffffffffu, s, 2);
            q += __shfl_xor_sync(0xffffffffu, q, 2);
            if (lm == 0) {
                const int R = 32 * rg + 16 * mi + 8 * h + lq;
                sts64f(sLN + (uint32_t)(cg * 128 + R) * 8, s, q);
            }
        }
        gsync(mb0 + 24, ph);                  // (e) LN partials visible

        // prefetch next tile's efeat into staging (overlaps epilogue2b)
        if (tile + GRID_E < ETILES)
            prefetch_efeat_grp(sSTG, efeat, tile + GRID_E, rg, gt);

        // epilogue2b: normalize, affine, + residual efeat (L2-hot), store
#pragma unroll
        for (int mi = 0; mi < 2; mi++)
#pragma unroll
        for (int h = 0; h < 2; h++) {
            const int R = 32 * rg + 16 * mi + 8 * h + lq;
            const int e = base + R;
            const bool v = vr[mi * 2 + h];
            float2 p0 = *(float2*)(smem + (sLN - sb) + (uint32_t)R * 8);
            float2 p1 = *(float2*)(smem + (sLN - sb) + (uint32_t)(128 + R) * 8);
            float2 p2 = *(float2*)(smem + (sLN - sb) + (uint32_t)(256 + R) * 8);
            float2 p3 = *(float2*)(smem + (sLN - sb) + (uint32_t)(384 + R) * 8);
            const float mu  = (p0.x + p1.x + p2.x + p3.x) * 0.0078125f;
            const float var = (p0.y + p1.y + p2.y + p3.y) * 0.0078125f - mu * mu;
            const float rs  = rsqrtf(var + 1e-5f);
            const float4* pe = (const float4*)(efeat + (size_t)(v ? e : 0) * 128 + Lb);
            float4 r0 = v ? __ldg(pe)     : make_float4(0.f, 0.f, 0.f, 0.f);
            float4 r1 = v ? __ldg(pe + 1) : make_float4(0.f, 0.f, 0.f, 0.f);
            float4 o0, o1;
            o0.x = (ACCJ(mi, h, 0) - mu) * rs * ga0.x + be0.x + r0.x;
            o0.y = (ACCJ(mi, h, 1) - mu) * rs * ga0.y + be0.y + r0.y;
            o0.z = (ACCJ(mi, h, 2) - mu) * rs * ga0.z + be0.z + r0.z;
            o0.w = (ACCJ(mi, h, 3) - mu) * rs * ga0.w + be0.w + r0.w;
            o1.x = (ACCJ(mi, h, 4) - mu) * rs * ga1.x + be1.x + r1.x;
            o1.y = (ACCJ(mi, h, 5) - mu) * rs * ga1.y + be1.y + r1.y;
            o1.z = (ACCJ(mi, h, 6) - mu) * rs * ga1.z + be1.z + r1.z;
            o1.w = (ACCJ(mi, h, 7) - mu) * rs * ga1.w + be1.w + r1.w;
            if (v) {
                float4* po = (float4*)(out + (size_t)e * 128 + Lb);
                po[0] = o0; po[1] = o1;
            }
        }
        ph ^= 1;                              // all 4 barriers used once per tile
    }
}

// ---------------- launch ----------------

extern "C" void kernel_launch(void* const* d_in, const int* in_sizes, int n_in,
                              void* d_out, int out_size) {
    const float* efeat = (const float*)d_in[0];
    const float* nfeat = (const float*)d_in[1];
    const int*   src   = (const int*)d_in[2];
    const int*   dst   = (const int*)d_in[3];
    const float* We    = (const float*)d_in[4];
    const float* Ws    = (const float*)d_in[5];
    const float* Wd    = (const float*)d_in[6];
    const float* b1    = (const float*)d_in[7];
    const float* Wo    = (const float*)d_in[8];
    const float* bo    = (const float*)d_in[9];
    const float* gamma = (const float*)d_in[10];
    const float* beta  = (const float*)d_in[11];
    float* out = (float*)d_out;

    cudaFuncSetAttribute(node_kernel, cudaFuncAttributeMaxDynamicSharedMemorySize, NODE_SMEM);
    cudaFuncSetAttribute(edge_kernel, cudaFuncAttributeMaxDynamicSharedMemorySize, EDGE_SMEM);

    // node kernel also writes the nfeat passthrough output
    node_kernel<<<NTILES, 512, NODE_SMEM>>>(nfeat, Ws, Wd, b1,
                                            out + (size_t)N_EDGES * 128);
    edge_kernel<<<GRID_E, 512, EDGE_SMEM>>>(efeat, src, dst, We, Wo, bo, gamma, beta, out);
}